// round 8
// baseline (speedup 1.0000x reference)
#include <cuda_runtime.h>

#define BATCH 32
#define NPTS 512
#define DIM 1024
#define KCL 64
#define NROWS (BATCH*NPTS)      /* 16384 */
#define OUTF 1024
#define IN2 (2*DIM*KCL)         /* 131072 */
#define HALF1 (DIM*KCL)         /* 65536 */

// ---------------- scratch (device globals: no allocations allowed) ----------
__device__ float g_act[NROWS*KCL];          // 4 MB
__device__ float g_colsum[KCL];
__device__ float g_colsumsq[KCL];
__device__ float g_asum[BATCH*KCL];
__device__ float g_fv1[BATCH*DIM*KCL];      // 8 MB
__device__ float g_fv2[BATCH*DIM*KCL];      // 8 MB
__device__ float g_colnorm[BATCH*KCL];
__device__ float g_norm2[BATCH];
__device__ float g_scale1[BATCH*KCL];
__device__ float g_scale2[BATCH];
__device__ float g_fvout[BATCH*OUTF];
__device__ float g_gates[BATCH*OUTF];

typedef unsigned long long ull;

// ---------------- f32x2 helpers (FFMA2: 2 FMAs / instr on sm_103a) ----------
__device__ __forceinline__ ull pack2(float lo, float hi){
  ull r;
  asm("mov.b64 %0, {%1, %2};" : "=l"(r)
      : "r"(__float_as_uint(lo)), "r"(__float_as_uint(hi)));
  return r;
}
__device__ __forceinline__ void ffma2(ull &d, ull a, ull b){
  asm("fma.rn.f32x2 %0, %1, %2, %3;" : "=l"(d) : "l"(a), "l"(b), "l"(d));
}
__device__ __forceinline__ ull mul2(ull a, ull b){
  ull r; asm("mul.rn.f32x2 %0, %1, %2;" : "=l"(r) : "l"(a), "l"(b)); return r;
}
__device__ __forceinline__ float lo32(ull v){ return __uint_as_float((unsigned)(v & 0xffffffffull)); }
__device__ __forceinline__ float hi32(ull v){ return __uint_as_float((unsigned)(v >> 32)); }

// ---------------- K0: zero the atomic accumulators ---------------------------
__global__ void zero_kernel(){
  int i = blockIdx.x*blockDim.x + threadIdx.x;
  if (i < BATCH*OUTF){ g_fvout[i] = 0.f; g_gates[i] = 0.f; }
  if (i < BATCH*KCL){ g_colnorm[i] = 0.f; g_asum[i] = 0.f; }
  if (i < KCL){ g_colsum[i] = 0.f; g_colsumsq[i] = 0.f; }
  if (i < BATCH) g_norm2[i] = 0.f;
}

// ---------------- K1: act_raw = X @ Wc  (+ column sum / sumsq for BN1) ------
__global__ __launch_bounds__(256) void gemm_act_kernel(
    const float* __restrict__ x, const float* __restrict__ wc){
  __shared__ float As[64][33];
  __shared__ float Bs[32][64];
  __shared__ float sSum[KCL], sSq[KCL];
  int tid = threadIdx.x;
  int row0 = blockIdx.x * 64;
  int tx = tid & 15, ty = tid >> 4;
  ull acc[4][2];
  #pragma unroll
  for (int i=0;i<4;i++){ acc[i][0]=0ull; acc[i][1]=0ull; }
  if (tid < KCL){ sSum[tid]=0.f; sSq[tid]=0.f; }

  for (int d0=0; d0<DIM; d0+=32){
    #pragma unroll
    for (int l=tid; l<2048; l+=256){
      int r=l>>5, c=l&31;
      As[r][c] = x[(row0+r)*DIM + d0 + c];
    }
    #pragma unroll
    for (int l=tid; l<2048; l+=256){
      int r=l>>6, c=l&63;
      Bs[r][c] = wc[(d0+r)*KCL + c];
    }
    __syncthreads();
    #pragma unroll
    for (int dd=0; dd<32; dd++){
      const ull* bp = reinterpret_cast<const ull*>(&Bs[dd][tx*4]);
      ull b0 = bp[0], b1 = bp[1];
      #pragma unroll
      for (int i=0;i<4;i++){
        float a = As[ty*4+i][dd];
        ull ap = pack2(a, a);
        ffma2(acc[i][0], ap, b0);
        ffma2(acc[i][1], ap, b1);
      }
    }
    __syncthreads();
  }
  float ps[4]={0,0,0,0}, pq[4]={0,0,0,0};
  #pragma unroll
  for (int i=0;i<4;i++){
    float v0=lo32(acc[i][0]), v1=hi32(acc[i][0]);
    float v2=lo32(acc[i][1]), v3=hi32(acc[i][1]);
    *reinterpret_cast<float4*>(&g_act[(row0+ty*4+i)*KCL + tx*4]) =
        make_float4(v0,v1,v2,v3);
    ps[0]+=v0; ps[1]+=v1; ps[2]+=v2; ps[3]+=v3;
    pq[0]+=v0*v0; pq[1]+=v1*v1; pq[2]+=v2*v2; pq[3]+=v3*v3;
  }
  #pragma unroll
  for (int j=0;j<4;j++){
    atomicAdd(&sSum[tx*4+j], ps[j]);
    atomicAdd(&sSq [tx*4+j], pq[j]);
  }
  __syncthreads();
  if (tid < KCL){
    atomicAdd(&g_colsum[tid],   sSum[tid]);
    atomicAdd(&g_colsumsq[tid], sSq[tid]);
  }
}

// ---------------- K2: BN1 + softmax (warp per row) + fused a_sum ------------
__global__ __launch_bounds__(256) void bn_softmax_kernel(
    const float* __restrict__ gamma, const float* __restrict__ beta){
  __shared__ float sbuf[8][KCL];
  int tid = threadIdx.x;
  int w = tid >> 5, lane = tid & 31;
  int row = blockIdx.x*8 + w;
  int b = row >> 9;
  const float inv_n = 1.f / (float)NROWS;
  int k2 = 2*lane;
  float2 cs = *reinterpret_cast<const float2*>(&g_colsum[k2]);
  float2 cq = *reinterpret_cast<const float2*>(&g_colsumsq[k2]);
  float2 ga = *reinterpret_cast<const float2*>(&gamma[k2]);
  float2 be = *reinterpret_cast<const float2*>(&beta[k2]);
  float m0 = cs.x*inv_n, m1 = cs.y*inv_n;
  float sc0 = ga.x*rsqrtf(cq.x*inv_n - m0*m0 + 1e-5f);
  float sc1 = ga.y*rsqrtf(cq.y*inv_n - m1*m1 + 1e-5f);
  float sh0 = be.x - m0*sc0, sh1 = be.y - m1*sc1;

  float2 v = *reinterpret_cast<const float2*>(&g_act[row*KCL + k2]);
  float vn0 = v.x*sc0 + sh0, vn1 = v.y*sc1 + sh1;
  float mx = fmaxf(vn0, vn1);
  #pragma unroll
  for (int o=16;o>0;o>>=1) mx = fmaxf(mx, __shfl_xor_sync(0xffffffffu, mx, o));
  float e0 = __expf(vn0 - mx), e1 = __expf(vn1 - mx);
  float s = e0 + e1;
  #pragma unroll
  for (int o=16;o>0;o>>=1) s += __shfl_xor_sync(0xffffffffu, s, o);
  float inv = 1.f / s;
  float p0 = e0*inv, p1 = e1*inv;
  *reinterpret_cast<float2*>(&g_act[row*KCL + k2]) = make_float2(p0, p1);
  *reinterpret_cast<float2*>(&sbuf[w][k2]) = make_float2(p0, p1);
  __syncthreads();
  if (tid < KCL){
    float t = 0.f;
    #pragma unroll
    for (int i=0;i<8;i++) t += sbuf[i][tid];
    atomicAdd(&g_asum[b*KCL + tid], t);
  }
}

// ---------------- K4: einsum + fused covariance transform + norm partials ---
// grid (16 dtiles, 32 b), block 128. tile 64d x 64k, thread 8d x 4k, NT=32.
// act staged in smem pre-duplicated as f32x2 (kills pack2 in inner loop).
__global__ __launch_bounds__(128) void einsum_kernel(
    const float* __restrict__ x,
    const float* __restrict__ covw, const float* __restrict__ cw2w){
  __shared__ float xs[32][64];
  __shared__ ull  as2[32][64];
  __shared__ float sCol[KCL];
  __shared__ float swp[4];
  int tid = threadIdx.x;
  int b = blockIdx.y, dt0 = blockIdx.x*64;
  int kg = tid & 15, dg = tid >> 4;      // 16 x 8
  int k0 = kg*4, d0 = dg*8;
  ull f1[4][4], f2[4][4];                // [k][d-ull pair]
  #pragma unroll
  for (int kk=0;kk<4;kk++)
    #pragma unroll
    for (int j=0;j<4;j++){ f1[kk][j]=0ull; f2[kk][j]=0ull; }

  for (int n0=0; n0<NPTS; n0+=32){
    #pragma unroll
    for (int l=tid; l<512; l+=128){
      int r = l>>4, c = (l&15)*4;
      *reinterpret_cast<float4*>(&xs[r][c]) =
          *reinterpret_cast<const float4*>(&x[(b*NPTS + n0 + r)*DIM + dt0 + c]);
      float4 av = *reinterpret_cast<const float4*>(&g_act[(b*NPTS + n0 + r)*KCL + c]);
      as2[r][c  ] = pack2(av.x, av.x);
      as2[r][c+1] = pack2(av.y, av.y);
      as2[r][c+2] = pack2(av.z, av.z);
      as2[r][c+3] = pack2(av.w, av.w);
    }
    __syncthreads();
    #pragma unroll
    for (int nn=0; nn<32; nn++){
      const ull* xp = reinterpret_cast<const ull*>(&xs[nn][d0]);
      ull xv[4], qv[4];
      #pragma unroll
      for (int j=0;j<4;j++){ xv[j] = xp[j]; qv[j] = mul2(xv[j], xv[j]); }
      const ull* ap = &as2[nn][k0];
      ull a0 = ap[0], a1 = ap[1], a2 = ap[2], a3 = ap[3];
      #pragma unroll
      for (int j=0;j<4;j++){
        ffma2(f1[0][j], xv[j], a0); ffma2(f1[1][j], xv[j], a1);
        ffma2(f1[2][j], xv[j], a2); ffma2(f1[3][j], xv[j], a3);
        ffma2(f2[0][j], qv[j], a0); ffma2(f2[1][j], qv[j], a1);
        ffma2(f2[2][j], qv[j], a2); ffma2(f2[3][j], qv[j], a3);
      }
    }
    __syncthreads();
  }

  // ---- fused transform epilogue (was fv_transform_kernel) ----
  float4 asv = *reinterpret_cast<const float4*>(&g_asum[b*KCL + k0]);
  float asm_[4] = {asv.x, asv.y, asv.z, asv.w};
  float pcol[4] = {0.f,0.f,0.f,0.f};
  float pn2 = 0.f;
  #pragma unroll
  for (int j=0;j<4;j++){
    int dbase = dt0 + d0 + j*2;
    #pragma unroll
    for (int h=0; h<2; h++){
      int dd = dbase + h;
      float4 cw = *reinterpret_cast<const float4*>(&cw2w[dd*KCL + k0]);
      float4 cv = *reinterpret_cast<const float4*>(&covw[dd*KCL + k0]);
      float f1v[4], f2v[4];
      #pragma unroll
      for (int m=0;m<4;m++){
        f1v[m] = h ? hi32(f1[m][j]) : lo32(f1[m][j]);
        f2v[m] = h ? hi32(f2[m][j]) : lo32(f2[m][j]);
      }
      float o1[4], o2[4];
      const float* cwp = &cw.x;
      const float* cvp = &cv.x;
      #pragma unroll
      for (int m=0;m<4;m++){
        float cwm = cwp[m], cvm = cvp[m];
        float cwv = cvm*cvm + 1e-6f;
        float rc = __fdividef(1.f, cwv);
        float f1t = (f1v[m] - asm_[m]*cwm) * rc;
        float f2t = (asm_[m]*cwm*cwm + f2v[m] - 2.f*f1v[m]*cwm) * rc * rc - asm_[m];
        o1[m] = f1t; o2[m] = f2t;
        pcol[m] += f1t*f1t; pn2 += f2t*f2t;
      }
      *reinterpret_cast<float4*>(&g_fv1[(b*DIM + dd)*KCL + k0]) =
          make_float4(o1[0],o1[1],o1[2],o1[3]);
      *reinterpret_cast<float4*>(&g_fv2[(b*DIM + dd)*KCL + k0]) =
          make_float4(o2[0],o2[1],o2[2],o2[3]);
    }
  }
  // block reductions
  if (tid < KCL) sCol[tid] = 0.f;
  __syncthreads();
  #pragma unroll
  for (int m=0;m<4;m++) atomicAdd(&sCol[k0+m], pcol[m]);
  #pragma unroll
  for (int o=16;o>0;o>>=1) pn2 += __shfl_xor_sync(0xffffffffu, pn2, o);
  if ((tid&31)==0) swp[tid>>5] = pn2;
  __syncthreads();
  if (tid < KCL) atomicAdd(&g_colnorm[b*KCL + tid], sCol[tid]);
  if (tid == 0)
    atomicAdd(&g_norm2[b], swp[0]+swp[1]+swp[2]+swp[3]);
}

// ---------------- K5b: tiny — fold the two-stage norms into scale tables ----
__global__ __launch_bounds__(64) void scale_kernel(){
  int b = blockIdx.x, k = threadIdx.x;
  float cn = g_colnorm[b*KCL + k];
  float inv1 = 1.f / fmaxf(sqrtf(cn), 1e-12f);
  float contrib = cn * inv1 * inv1;
  float t = contrib;
  #pragma unroll
  for (int o=16;o>0;o>>=1) t += __shfl_xor_sync(0xffffffffu, t, o);
  __shared__ float sw[2];
  if ((k&31)==0) sw[k>>5] = t;
  __syncthreads();
  float n1 = sqrtf(sw[0] + sw[1]);
  g_scale1[b*KCL + k] = inv1 / fmaxf(n1, 1e-12f);
  if (k == 0) g_scale2[b] = 1.f / fmaxf(sqrtf(g_norm2[b]), 1e-12f);
}

// ---------------- K6/K7a: out[32,1024] += A[32,chunk] @ W[chunk,1024] -------
// Double-buffered smem + register prefetch, thread tile 8b x 4o:
// per ii = 1 w-LDS.128 + 2 broadcasts for 16 ffma2 -> fma-issue-bound.
// og = tid&63 (cols og*4, exact cover of 256), bg = tid>>6 (8 b each).
#define FC_KT 8
__global__ __launch_bounds__(256) void gemm_fc_kernel(
    const float* __restrict__ W, int ichunk, int which){
  __shared__ float Ws[2][FC_KT][256];
  __shared__ float fs[2][FC_KT][32];
  __shared__ float scl[BATCH*KCL];
  int tid = threadIdx.x;
  int o0 = blockIdx.x * 256;
  int i0 = blockIdx.y * ichunk;
  int og = tid & 63, bg = tid >> 6;  // 64 o-groups x 4 b-groups
  const float* A; float* out;
  int Alda, iA0; int half1 = 0;
  float sc2 = 1.f;
  int bload = tid & 31;              // batch row this thread loads
  int rload = tid >> 5;              // k-row this thread loads
  if (which == 0){
    out = g_fvout; Alda = HALF1;
    if (i0 < HALF1){ A = g_fv1; iA0 = i0; half1 = 1; }
    else { A = g_fv2; iA0 = i0 - HALF1; sc2 = g_scale2[bload]; }
    if (half1){
      for (int l = tid; l < BATCH*KCL; l += 256) scl[l] = g_scale1[l];
    }
  } else {
    A = g_fvout; out = g_gates; Alda = OUTF; iA0 = i0;
  }
  __syncthreads();

  int T = ichunk / FC_KT;
  int off0 = tid*4;
  int r0 = off0 >> 8,  c0 = off0 & 255;
  int off1 = 1024 + tid*4;
  int r1 = off1 >> 8,  c1 = off1 & 255;

  ull acc[8][2];
  #pragma unroll
  for (int bb=0;bb<8;bb++){ acc[bb][0]=0ull; acc[bb][1]=0ull; }

  // prefetch tile 0
  float4 pw0, pw1; float pa;
  {
    int i = i0;
    pw0 = *reinterpret_cast<const float4*>(&W[(i+r0)*OUTF + o0 + c0]);
    pw1 = *reinterpret_cast<const float4*>(&W[(i+r1)*OUTF + o0 + c1]);
    float v = A[bload*Alda + iA0 + rload];
    if (which == 0){
      if (half1) v *= scl[bload*KCL + ((iA0 + rload) & 63)];
      else       v *= sc2;
    }
    pa = v;
  }
  *reinterpret_cast<float4*>(&Ws[0][r0][c0]) = pw0;
  *reinterpret_cast<float4*>(&Ws[0][r1][c1]) = pw1;
  fs[0][rload][bload] = pa;
  __syncthreads();

  for (int t=0; t<T; t++){
    int cur = t & 1;
    bool more = (t+1) < T;
    if (more){
      int i  = i0  + (t+1)*FC_KT;
      int iA = iA0 + (t+1)*FC_KT;
      pw0 = *reinterpret_cast<const float4*>(&W[(i+r0)*OUTF + o0 + c0]);
      pw1 = *reinterpret_cast<const float4*>(&W[(i+r1)*OUTF + o0 + c1]);
      float v = A[bload*Alda + iA + rload];
      if (which == 0){
        if (half1) v *= scl[bload*KCL + ((iA + rload) & 63)];
        else       v *= sc2;
      }
      pa = v;
    }
    #pragma unroll
    for (int ii=0; ii<FC_KT; ii++){
      const ull* wp = reinterpret_cast<const ull*>(&Ws[cur][ii][og*4]);
      ull w0 = wp[0], w1 = wp[1];
      float4 fa = *reinterpret_cast<const float4*>(&fs[cur][ii][bg*8]);
      float4 fb = *reinterpret_cast<const float4*>(&fs[cur][ii][bg*8+4]);
      ull a0 = pack2(fa.x,fa.x), a1 = pack2(fa.y,fa.y);
      ull a2 = pack2(fa.z,fa.z), a3 = pack2(fa.w,fa.w);
      ull a4 = pack2(fb.x,fb.x), a5 = pack2(fb.y,fb.y);
      ull a6 = pack2(fb.z,fb.z), a7 = pack2(fb.w,fb.w);
      ffma2(acc[0][0], a0, w0); ffma2(acc[0][1], a0, w1);
      ffma2(acc[1][0], a1, w0); ffma2(acc[1][1], a1, w1);
      ffma2(acc[2][0], a2, w0); ffma2(acc[2][1], a2, w1);
      ffma2(acc[3][0], a3, w0); ffma2(acc[3][1], a3, w1);
      ffma2(acc[4][0], a4, w0); ffma2(acc[4][1], a4, w1);
      ffma2(acc[5][0], a5, w0); ffma2(acc[5][1], a5, w1);
      ffma2(acc[6][0], a6, w0); ffma2(acc[6][1], a6, w1);
      ffma2(acc[7][0], a7, w0); ffma2(acc[7][1], a7, w1);
    }
    if (more){
      int nxt = (t+1) & 1;
      *reinterpret_cast<float4*>(&Ws[nxt][r0][c0]) = pw0;
      *reinterpret_cast<float4*>(&Ws[nxt][r1][c1]) = pw1;
      fs[nxt][rload][bload] = pa;
    }
    __syncthreads();
  }

  #pragma unroll
  for (int bb=0;bb<8;bb++){
    int b = bg*8 + bb;
    #pragma unroll
    for (int t=0;t<2;t++){
      int base = b*OUTF + o0 + og*4 + t*2;
      atomicAdd(&out[base],   lo32(acc[bb][t]));
      atomicAdd(&out[base+1], hi32(acc[bb][t]));
    }
  }
}

// ---------------- K7b: BN2 (batch stats over 32) + sigmoid gate -------------
__global__ __launch_bounds__(256) void bn2_gate_kernel(
    const float* __restrict__ g2, const float* __restrict__ b2,
    float* __restrict__ out){
  int o = blockIdx.x*blockDim.x + threadIdx.x;   // 0..1023
  float m=0.f, s=0.f;
  #pragma unroll 8
  for (int b=0;b<BATCH;b++){ float v = g_gates[b*OUTF + o]; m += v; s += v*v; }
  m *= (1.f/BATCH);
  float var = s*(1.f/BATCH) - m*m;
  float rs = rsqrtf(var + 1e-5f);
  float ga = g2[o], be = b2[o];
  #pragma unroll 8
  for (int b=0;b<BATCH;b++){
    float v = (g_gates[b*OUTF + o] - m)*rs*ga + be;
    float sig = 1.f/(1.f + expf(-v));
    out[b*OUTF + o] = g_fvout[b*OUTF + o] * sig;
  }
}

// ---------------------------------------------------------------------------
extern "C" void kernel_launch(void* const* d_in, const int* in_sizes, int n_in,
                              void* d_out, int out_size){
  const float* x   = (const float*)d_in[0];   // [32,512,1024]
  const float* wc  = (const float*)d_in[1];   // [1024,64]
  const float* cov = (const float*)d_in[2];   // [1024,64]
  const float* cw2 = (const float*)d_in[3];   // [1,1024,64]
  const float* w1  = (const float*)d_in[4];   // [131072,1024]
  const float* g1  = (const float*)d_in[5];   // [64]
  const float* b1  = (const float*)d_in[6];   // [64]
  const float* wg  = (const float*)d_in[7];   // [1024,1024]
  const float* g2  = (const float*)d_in[8];   // [1024]
  const float* b2  = (const float*)d_in[9];   // [1024]
  float* out = (float*)d_out;                 // [32,1024]

  zero_kernel<<<128, 256>>>();
  gemm_act_kernel<<<256, 256>>>(x, wc);
  bn_softmax_kernel<<<2048, 256>>>(g1, b1);
  einsum_kernel<<<dim3(16, 32), 128>>>(x, cov, cw2);
  scale_kernel<<<BATCH, 64>>>();
  gemm_fc_kernel<<<dim3(4, 64), 256>>>(w1, 2048, 0);  // hidden1
  gemm_fc_kernel<<<dim3(4, 8),  256>>>(wg, 128, 1);   // gating
  bn2_gate_kernel<<<4, 256>>>(g2, b2, out);
}

// round 9
// speedup vs baseline: 1.1323x; 1.1323x over previous
#include <cuda_runtime.h>

#define BATCH 32
#define NPTS 512
#define DIM 1024
#define KCL 64
#define NROWS (BATCH*NPTS)      /* 16384 */
#define OUTF 1024
#define IN2 (2*DIM*KCL)         /* 131072 */
#define HALF1 (DIM*KCL)         /* 65536 */

// ---------------- scratch (device globals: no allocations allowed) ----------
__device__ float g_act[NROWS*KCL];          // 4 MB
__device__ float g_colsum[KCL];
__device__ float g_colsumsq[KCL];
__device__ float g_asum[BATCH*KCL];
__device__ float g_fv1[BATCH*DIM*KCL];      // 8 MB
__device__ float g_fv2[BATCH*DIM*KCL];      // 8 MB
__device__ float g_colnorm[BATCH*KCL];
__device__ float g_norm2[BATCH];
__device__ float g_scale1[BATCH*KCL];
__device__ float g_scale2[BATCH];
__device__ float g_fvout[BATCH*OUTF];
__device__ float g_gates[BATCH*OUTF];

typedef unsigned long long ull;

// ---------------- f32x2 helpers (FFMA2: 2 FMAs / instr on sm_103a) ----------
__device__ __forceinline__ ull pack2(float lo, float hi){
  ull r;
  asm("mov.b64 %0, {%1, %2};" : "=l"(r)
      : "r"(__float_as_uint(lo)), "r"(__float_as_uint(hi)));
  return r;
}
__device__ __forceinline__ void ffma2(ull &d, ull a, ull b){
  asm("fma.rn.f32x2 %0, %1, %2, %3;" : "=l"(d) : "l"(a), "l"(b), "l"(d));
}
__device__ __forceinline__ ull mul2(ull a, ull b){
  ull r; asm("mul.rn.f32x2 %0, %1, %2;" : "=l"(r) : "l"(a), "l"(b)); return r;
}
__device__ __forceinline__ float lo32(ull v){ return __uint_as_float((unsigned)(v & 0xffffffffull)); }
__device__ __forceinline__ float hi32(ull v){ return __uint_as_float((unsigned)(v >> 32)); }

// ---------------- K0: zero the atomic accumulators ---------------------------
__global__ void zero_kernel(){
  int i = blockIdx.x*blockDim.x + threadIdx.x;
  if (i < BATCH*OUTF){ g_fvout[i] = 0.f; g_gates[i] = 0.f; }
  if (i < BATCH*KCL){ g_colnorm[i] = 0.f; g_asum[i] = 0.f; }
  if (i < KCL){ g_colsum[i] = 0.f; g_colsumsq[i] = 0.f; }
  if (i < BATCH) g_norm2[i] = 0.f;
}

// ---------------- K1: act_raw = X @ Wc  (+ column sum / sumsq for BN1) ------
__global__ __launch_bounds__(256) void gemm_act_kernel(
    const float* __restrict__ x, const float* __restrict__ wc){
  __shared__ float As[64][33];
  __shared__ float Bs[32][64];
  __shared__ float sSum[KCL], sSq[KCL];
  int tid = threadIdx.x;
  int row0 = blockIdx.x * 64;
  int tx = tid & 15, ty = tid >> 4;
  ull acc[4][2];
  #pragma unroll
  for (int i=0;i<4;i++){ acc[i][0]=0ull; acc[i][1]=0ull; }
  if (tid < KCL){ sSum[tid]=0.f; sSq[tid]=0.f; }

  for (int d0=0; d0<DIM; d0+=32){
    #pragma unroll
    for (int l=tid; l<2048; l+=256){
      int r=l>>5, c=l&31;
      As[r][c] = x[(row0+r)*DIM + d0 + c];
    }
    #pragma unroll
    for (int l=tid; l<2048; l+=256){
      int r=l>>6, c=l&63;
      Bs[r][c] = wc[(d0+r)*KCL + c];
    }
    __syncthreads();
    #pragma unroll
    for (int dd=0; dd<32; dd++){
      const ull* bp = reinterpret_cast<const ull*>(&Bs[dd][tx*4]);
      ull b0 = bp[0], b1 = bp[1];
      #pragma unroll
      for (int i=0;i<4;i++){
        float a = As[ty*4+i][dd];
        ull ap = pack2(a, a);
        ffma2(acc[i][0], ap, b0);
        ffma2(acc[i][1], ap, b1);
      }
    }
    __syncthreads();
  }
  float ps[4]={0,0,0,0}, pq[4]={0,0,0,0};
  #pragma unroll
  for (int i=0;i<4;i++){
    float v0=lo32(acc[i][0]), v1=hi32(acc[i][0]);
    float v2=lo32(acc[i][1]), v3=hi32(acc[i][1]);
    *reinterpret_cast<float4*>(&g_act[(row0+ty*4+i)*KCL + tx*4]) =
        make_float4(v0,v1,v2,v3);
    ps[0]+=v0; ps[1]+=v1; ps[2]+=v2; ps[3]+=v3;
    pq[0]+=v0*v0; pq[1]+=v1*v1; pq[2]+=v2*v2; pq[3]+=v3*v3;
  }
  #pragma unroll
  for (int j=0;j<4;j++){
    atomicAdd(&sSum[tx*4+j], ps[j]);
    atomicAdd(&sSq [tx*4+j], pq[j]);
  }
  __syncthreads();
  if (tid < KCL){
    atomicAdd(&g_colsum[tid],   sSum[tid]);
    atomicAdd(&g_colsumsq[tid], sSq[tid]);
  }
}

// ---------------- K2: BN1 + softmax (warp per row) + fused a_sum ------------
__global__ __launch_bounds__(256) void bn_softmax_kernel(
    const float* __restrict__ gamma, const float* __restrict__ beta){
  __shared__ float sbuf[8][KCL];
  int tid = threadIdx.x;
  int w = tid >> 5, lane = tid & 31;
  int row = blockIdx.x*8 + w;
  int b = row >> 9;
  const float inv_n = 1.f / (float)NROWS;
  int k2 = 2*lane;
  float2 cs = *reinterpret_cast<const float2*>(&g_colsum[k2]);
  float2 cq = *reinterpret_cast<const float2*>(&g_colsumsq[k2]);
  float2 ga = *reinterpret_cast<const float2*>(&gamma[k2]);
  float2 be = *reinterpret_cast<const float2*>(&beta[k2]);
  float m0 = cs.x*inv_n, m1 = cs.y*inv_n;
  float sc0 = ga.x*rsqrtf(cq.x*inv_n - m0*m0 + 1e-5f);
  float sc1 = ga.y*rsqrtf(cq.y*inv_n - m1*m1 + 1e-5f);
  float sh0 = be.x - m0*sc0, sh1 = be.y - m1*sc1;

  float2 v = *reinterpret_cast<const float2*>(&g_act[row*KCL + k2]);
  float vn0 = v.x*sc0 + sh0, vn1 = v.y*sc1 + sh1;
  float mx = fmaxf(vn0, vn1);
  #pragma unroll
  for (int o=16;o>0;o>>=1) mx = fmaxf(mx, __shfl_xor_sync(0xffffffffu, mx, o));
  float e0 = __expf(vn0 - mx), e1 = __expf(vn1 - mx);
  float s = e0 + e1;
  #pragma unroll
  for (int o=16;o>0;o>>=1) s += __shfl_xor_sync(0xffffffffu, s, o);
  float inv = 1.f / s;
  float p0 = e0*inv, p1 = e1*inv;
  *reinterpret_cast<float2*>(&g_act[row*KCL + k2]) = make_float2(p0, p1);
  *reinterpret_cast<float2*>(&sbuf[w][k2]) = make_float2(p0, p1);
  __syncthreads();
  if (tid < KCL){
    float t = 0.f;
    #pragma unroll
    for (int i=0;i<8;i++) t += sbuf[i][tid];
    atomicAdd(&g_asum[b*KCL + tid], t);
  }
}

// ---------------- K4: einsum + fused covariance transform + norm partials ---
// grid (16 dtiles, 32 b), block 128. tile 64d x 64k, thread 8d x 4k, NT=32.
// (round-7 form: act as float in smem, pack2 in registers)
__global__ __launch_bounds__(128) void einsum_kernel(
    const float* __restrict__ x,
    const float* __restrict__ covw, const float* __restrict__ cw2w){
  __shared__ float xs[32][64];
  __shared__ float as_[32][64];
  __shared__ float sCol[KCL];
  __shared__ float swp[4];
  int tid = threadIdx.x;
  int b = blockIdx.y, dt0 = blockIdx.x*64;
  int kg = tid & 15, dg = tid >> 4;      // 16 x 8
  int k0 = kg*4, d0 = dg*8;
  ull f1[4][4], f2[4][4];                // [k][d-ull pair]
  #pragma unroll
  for (int kk=0;kk<4;kk++)
    #pragma unroll
    for (int j=0;j<4;j++){ f1[kk][j]=0ull; f2[kk][j]=0ull; }

  for (int n0=0; n0<NPTS; n0+=32){
    #pragma unroll
    for (int l=tid; l<512; l+=128){
      int r = l>>4, c = (l&15)*4;
      *reinterpret_cast<float4*>(&xs[r][c]) =
          *reinterpret_cast<const float4*>(&x[(b*NPTS + n0 + r)*DIM + dt0 + c]);
      *reinterpret_cast<float4*>(&as_[r][c]) =
          *reinterpret_cast<const float4*>(&g_act[(b*NPTS + n0 + r)*KCL + c]);
    }
    __syncthreads();
    #pragma unroll
    for (int nn=0; nn<32; nn++){
      const ull* xp = reinterpret_cast<const ull*>(&xs[nn][d0]);
      ull xv[4], qv[4];
      #pragma unroll
      for (int j=0;j<4;j++){ xv[j] = xp[j]; qv[j] = mul2(xv[j], xv[j]); }
      float4 av = *reinterpret_cast<const float4*>(&as_[nn][k0]);
      ull a0 = pack2(av.x, av.x), a1 = pack2(av.y, av.y);
      ull a2 = pack2(av.z, av.z), a3 = pack2(av.w, av.w);
      #pragma unroll
      for (int j=0;j<4;j++){
        ffma2(f1[0][j], xv[j], a0); ffma2(f1[1][j], xv[j], a1);
        ffma2(f1[2][j], xv[j], a2); ffma2(f1[3][j], xv[j], a3);
        ffma2(f2[0][j], qv[j], a0); ffma2(f2[1][j], qv[j], a1);
        ffma2(f2[2][j], qv[j], a2); ffma2(f2[3][j], qv[j], a3);
      }
    }
    __syncthreads();
  }

  // ---- fused transform epilogue ----
  float4 asv = *reinterpret_cast<const float4*>(&g_asum[b*KCL + k0]);
  float asm_[4] = {asv.x, asv.y, asv.z, asv.w};
  float pcol[4] = {0.f,0.f,0.f,0.f};
  float pn2 = 0.f;
  #pragma unroll
  for (int j=0;j<4;j++){
    int dbase = dt0 + d0 + j*2;
    #pragma unroll
    for (int h=0; h<2; h++){
      int dd = dbase + h;
      float4 cw = *reinterpret_cast<const float4*>(&cw2w[dd*KCL + k0]);
      float4 cv = *reinterpret_cast<const float4*>(&covw[dd*KCL + k0]);
      float f1v[4], f2v[4];
      #pragma unroll
      for (int m=0;m<4;m++){
        f1v[m] = h ? hi32(f1[m][j]) : lo32(f1[m][j]);
        f2v[m] = h ? hi32(f2[m][j]) : lo32(f2[m][j]);
      }
      float o1[4], o2[4];
      const float* cwp = &cw.x;
      const float* cvp = &cv.x;
      #pragma unroll
      for (int m=0;m<4;m++){
        float cwm = cwp[m], cvm = cvp[m];
        float cwv = cvm*cvm + 1e-6f;
        float rc = __fdividef(1.f, cwv);
        float f1t = (f1v[m] - asm_[m]*cwm) * rc;
        float f2t = (asm_[m]*cwm*cwm + f2v[m] - 2.f*f1v[m]*cwm) * rc * rc - asm_[m];
        o1[m] = f1t; o2[m] = f2t;
        pcol[m] += f1t*f1t; pn2 += f2t*f2t;
      }
      *reinterpret_cast<float4*>(&g_fv1[(b*DIM + dd)*KCL + k0]) =
          make_float4(o1[0],o1[1],o1[2],o1[3]);
      *reinterpret_cast<float4*>(&g_fv2[(b*DIM + dd)*KCL + k0]) =
          make_float4(o2[0],o2[1],o2[2],o2[3]);
    }
  }
  // block reductions
  if (tid < KCL) sCol[tid] = 0.f;
  __syncthreads();
  #pragma unroll
  for (int m=0;m<4;m++) atomicAdd(&sCol[k0+m], pcol[m]);
  #pragma unroll
  for (int o=16;o>0;o>>=1) pn2 += __shfl_xor_sync(0xffffffffu, pn2, o);
  if ((tid&31)==0) swp[tid>>5] = pn2;
  __syncthreads();
  if (tid < KCL) atomicAdd(&g_colnorm[b*KCL + tid], sCol[tid]);
  if (tid == 0)
    atomicAdd(&g_norm2[b], swp[0]+swp[1]+swp[2]+swp[3]);
}

// ---------------- K5b: tiny — fold the two-stage norms into scale tables ----
__global__ __launch_bounds__(64) void scale_kernel(){
  int b = blockIdx.x, k = threadIdx.x;
  float cn = g_colnorm[b*KCL + k];
  float inv1 = 1.f / fmaxf(sqrtf(cn), 1e-12f);
  float contrib = cn * inv1 * inv1;
  float t = contrib;
  #pragma unroll
  for (int o=16;o>0;o>>=1) t += __shfl_xor_sync(0xffffffffu, t, o);
  __shared__ float sw[2];
  if ((k&31)==0) sw[k>>5] = t;
  __syncthreads();
  float n1 = sqrtf(sw[0] + sw[1]);
  g_scale1[b*KCL + k] = inv1 / fmaxf(n1, 1e-12f);
  if (k == 0) g_scale2[b] = 1.f / fmaxf(sqrtf(g_norm2[b]), 1e-12f);
}

// ---------------- K6/K7a: out[32,1024] += A[32,chunk] @ W[chunk,1024] -------
// Double-buffered smem + register prefetch, thread tile 8b x 4o, FC_KT=16:
// 128 syncs per block, 2048 SMSP-cyc compute per prefetch stage.
// og = tid&63 (cols og*4, exact cover of 256), bg = tid>>6 (8 b each).
#define FC_KT 16
__global__ __launch_bounds__(256) void gemm_fc_kernel(
    const float* __restrict__ W, int ichunk, int which){
  __shared__ float Ws[2][FC_KT][256];
  __shared__ float fs[2][FC_KT][32];
  __shared__ float scl[BATCH*KCL];
  int tid = threadIdx.x;
  int o0 = blockIdx.x * 256;
  int i0 = blockIdx.y * ichunk;
  int og = tid & 63, bg = tid >> 6;  // 64 o-groups x 4 b-groups
  const float* A; float* out;
  int Alda, iA0; int half1 = 0;
  float sc2 = 1.f;
  int bload = tid & 31;              // batch row this thread loads
  int rload0 = (tid >> 5)*2;         // 2 k-rows this thread loads for fs
  if (which == 0){
    out = g_fvout; Alda = HALF1;
    if (i0 < HALF1){ A = g_fv1; iA0 = i0; half1 = 1; }
    else { A = g_fv2; iA0 = i0 - HALF1; sc2 = g_scale2[bload]; }
    if (half1){
      for (int l = tid; l < BATCH*KCL; l += 256) scl[l] = g_scale1[l];
    }
  } else {
    A = g_fvout; out = g_gates; Alda = OUTF; iA0 = i0;
  }
  __syncthreads();

  int T = ichunk / FC_KT;
  // W tile: 16x256 floats = 4 float4 per thread
  int roff[4], coff[4];
  #pragma unroll
  for (int p=0;p<4;p++){
    int off = p*1024 + tid*4;
    roff[p] = off >> 8; coff[p] = off & 255;
  }

  ull acc[8][2];
  #pragma unroll
  for (int bb=0;bb<8;bb++){ acc[bb][0]=0ull; acc[bb][1]=0ull; }

  // prefetch tile 0
  float4 pw[4]; float pa0, pa1;
  {
    int i = i0;
    #pragma unroll
    for (int p=0;p<4;p++)
      pw[p] = *reinterpret_cast<const float4*>(&W[(i+roff[p])*OUTF + o0 + coff[p]]);
    float v0 = A[bload*Alda + iA0 + rload0];
    float v1 = A[bload*Alda + iA0 + rload0 + 1];
    if (which == 0){
      if (half1){
        v0 *= scl[bload*KCL + ((iA0 + rload0) & 63)];
        v1 *= scl[bload*KCL + ((iA0 + rload0 + 1) & 63)];
      } else { v0 *= sc2; v1 *= sc2; }
    }
    pa0 = v0; pa1 = v1;
  }
  #pragma unroll
  for (int p=0;p<4;p++)
    *reinterpret_cast<float4*>(&Ws[0][roff[p]][coff[p]]) = pw[p];
  fs[0][rload0][bload] = pa0;
  fs[0][rload0+1][bload] = pa1;
  __syncthreads();

  for (int t=0; t<T; t++){
    int cur = t & 1;
    bool more = (t+1) < T;
    if (more){
      int i  = i0  + (t+1)*FC_KT;
      int iA = iA0 + (t+1)*FC_KT;
      #pragma unroll
      for (int p=0;p<4;p++)
        pw[p] = *reinterpret_cast<const float4*>(&W[(i+roff[p])*OUTF + o0 + coff[p]]);
      float v0 = A[bload*Alda + iA + rload0];
      float v1 = A[bload*Alda + iA + rload0 + 1];
      if (which == 0){
        if (half1){
          v0 *= scl[bload*KCL + ((iA + rload0) & 63)];
          v1 *= scl[bload*KCL + ((iA + rload0 + 1) & 63)];
        } else { v0 *= sc2; v1 *= sc2; }
      }
      pa0 = v0; pa1 = v1;
    }
    #pragma unroll
    for (int ii=0; ii<FC_KT; ii++){
      const ull* wp = reinterpret_cast<const ull*>(&Ws[cur][ii][og*4]);
      ull w0 = wp[0], w1 = wp[1];
      float4 fa = *reinterpret_cast<const float4*>(&fs[cur][ii][bg*8]);
      float4 fb = *reinterpret_cast<const float4*>(&fs[cur][ii][bg*8+4]);
      ull a0 = pack2(fa.x,fa.x), a1 = pack2(fa.y,fa.y);
      ull a2 = pack2(fa.z,fa.z), a3 = pack2(fa.w,fa.w);
      ull a4 = pack2(fb.x,fb.x), a5 = pack2(fb.y,fb.y);
      ull a6 = pack2(fb.z,fb.z), a7 = pack2(fb.w,fb.w);
      ffma2(acc[0][0], a0, w0); ffma2(acc[0][1], a0, w1);
      ffma2(acc[1][0], a1, w0); ffma2(acc[1][1], a1, w1);
      ffma2(acc[2][0], a2, w0); ffma2(acc[2][1], a2, w1);
      ffma2(acc[3][0], a3, w0); ffma2(acc[3][1], a3, w1);
      ffma2(acc[4][0], a4, w0); ffma2(acc[4][1], a4, w1);
      ffma2(acc[5][0], a5, w0); ffma2(acc[5][1], a5, w1);
      ffma2(acc[6][0], a6, w0); ffma2(acc[6][1], a6, w1);
      ffma2(acc[7][0], a7, w0); ffma2(acc[7][1], a7, w1);
    }
    if (more){
      int nxt = (t+1) & 1;
      #pragma unroll
      for (int p=0;p<4;p++)
        *reinterpret_cast<float4*>(&Ws[nxt][roff[p]][coff[p]]) = pw[p];
      fs[nxt][rload0][bload] = pa0;
      fs[nxt][rload0+1][bload] = pa1;
    }
    __syncthreads();
  }

  #pragma unroll
  for (int bb=0;bb<8;bb++){
    int b = bg*8 + bb;
    #pragma unroll
    for (int t=0;t<2;t++){
      int base = b*OUTF + o0 + og*4 + t*2;
      atomicAdd(&out[base],   lo32(acc[bb][t]));
      atomicAdd(&out[base+1], hi32(acc[bb][t]));
    }
  }
}

// ---------------- K7b: BN2 (batch stats over 32) + sigmoid gate -------------
__global__ __launch_bounds__(256) void bn2_gate_kernel(
    const float* __restrict__ g2, const float* __restrict__ b2,
    float* __restrict__ out){
  int o = blockIdx.x*blockDim.x + threadIdx.x;   // 0..1023
  float m=0.f, s=0.f;
  #pragma unroll 8
  for (int b=0;b<BATCH;b++){ float v = g_gates[b*OUTF + o]; m += v; s += v*v; }
  m *= (1.f/BATCH);
  float var = s*(1.f/BATCH) - m*m;
  float rs = rsqrtf(var + 1e-5f);
  float ga = g2[o], be = b2[o];
  #pragma unroll 8
  for (int b=0;b<BATCH;b++){
    float v = (g_gates[b*OUTF + o] - m)*rs*ga + be;
    float sig = 1.f/(1.f + expf(-v));
    out[b*OUTF + o] = g_fvout[b*OUTF + o] * sig;
  }
}

// ---------------------------------------------------------------------------
extern "C" void kernel_launch(void* const* d_in, const int* in_sizes, int n_in,
                              void* d_out, int out_size){
  const float* x   = (const float*)d_in[0];   // [32,512,1024]
  const float* wc  = (const float*)d_in[1];   // [1024,64]
  const float* cov = (const float*)d_in[2];   // [1024,64]
  const float* cw2 = (const float*)d_in[3];   // [1,1024,64]
  const float* w1  = (const float*)d_in[4];   // [131072,1024]
  const float* g1  = (const float*)d_in[5];   // [64]
  const float* b1  = (const float*)d_in[6];   // [64]
  const float* wg  = (const float*)d_in[7];   // [1024,1024]
  const float* g2  = (const float*)d_in[8];   // [1024]
  const float* b2  = (const float*)d_in[9];   // [1024]
  float* out = (float*)d_out;                 // [32,1024]

  zero_kernel<<<128, 256>>>();
  gemm_act_kernel<<<256, 256>>>(x, wc);
  bn_softmax_kernel<<<2048, 256>>>(g1, b1);
  einsum_kernel<<<dim3(16, 32), 128>>>(x, cov, cw2);
  scale_kernel<<<BATCH, 64>>>();
  gemm_fc_kernel<<<dim3(4, 64), 256>>>(w1, 2048, 0);  // hidden1
  gemm_fc_kernel<<<dim3(4, 8),  256>>>(wg, 128, 1);   // gating
  bn2_gate_kernel<<<4, 256>>>(g2, b2, out);
}

// round 10
// speedup vs baseline: 1.6438x; 1.4516x over previous
#include <cuda_runtime.h>

#define BATCH 32
#define NPTS 512
#define DIM 1024
#define KCL 64
#define NROWS (BATCH*NPTS)      /* 16384 */
#define OUTF 1024
#define IN2 (2*DIM*KCL)         /* 131072 */
#define HALF1 (DIM*KCL)         /* 65536 */

// ---------------- scratch (device globals: no allocations allowed) ----------
__device__ float g_act[NROWS*KCL];          // 4 MB
__device__ float g_colsum[KCL];
__device__ float g_colsumsq[KCL];
__device__ float g_asum[BATCH*KCL];
__device__ float g_fv1[BATCH*DIM*KCL];      // 8 MB
__device__ float g_fv2[BATCH*DIM*KCL];      // 8 MB
__device__ float g_colnorm[BATCH*KCL];
__device__ float g_norm2[BATCH];
__device__ float g_scale1[BATCH*KCL];
__device__ float g_scale2[BATCH];
__device__ float g_fvout[BATCH*OUTF];
__device__ float g_gates[BATCH*OUTF];

typedef unsigned long long ull;
typedef unsigned int uint;

// ---------------- f32x2 helpers (FFMA2: 2 FMAs / instr on sm_103a) ----------
__device__ __forceinline__ ull pack2(float lo, float hi){
  ull r;
  asm("mov.b64 %0, {%1, %2};" : "=l"(r)
      : "r"(__float_as_uint(lo)), "r"(__float_as_uint(hi)));
  return r;
}
__device__ __forceinline__ void ffma2(ull &d, ull a, ull b){
  asm("fma.rn.f32x2 %0, %1, %2, %3;" : "=l"(d) : "l"(a), "l"(b), "l"(d));
}
__device__ __forceinline__ ull mul2(ull a, ull b){
  ull r; asm("mul.rn.f32x2 %0, %1, %2;" : "=l"(r) : "l"(a), "l"(b)); return r;
}
__device__ __forceinline__ float lo32(ull v){ return __uint_as_float((unsigned)(v & 0xffffffffull)); }
__device__ __forceinline__ float hi32(ull v){ return __uint_as_float((unsigned)(v >> 32)); }

// ---------------- bf16 split helpers ----------------------------------------
// hi-pack: lower16(result)=top16(a) (k), upper16(result)=top16(b) (k+1) -- exact trunc
__device__ __forceinline__ uint prmt_hi(float a, float b){
  uint r;
  asm("prmt.b32 %0, %1, %2, 0x7632;" : "=r"(r)
      : "r"(__float_as_uint(a)), "r"(__float_as_uint(b)));
  return r;
}
__device__ __forceinline__ float trunc_bf(float v){
  return __uint_as_float(__float_as_uint(v) & 0xffff0000u);
}
// pack (lo_first -> lower half, lo_second -> upper half)
__device__ __forceinline__ uint cvt_bf2(float upper, float lower){
  uint r;
  asm("cvt.rn.bf16x2.f32 %0, %1, %2;" : "=r"(r) : "f"(upper), "f"(lower));
  return r;
}
__device__ __forceinline__ void mma_bf16(float* c, const uint* a, uint b0, uint b1){
  asm volatile(
    "mma.sync.aligned.m16n8k16.row.col.f32.bf16.bf16.f32 "
    "{%0,%1,%2,%3},{%4,%5,%6,%7},{%8,%9},{%0,%1,%2,%3};"
    : "+f"(c[0]), "+f"(c[1]), "+f"(c[2]), "+f"(c[3])
    : "r"(a[0]), "r"(a[1]), "r"(a[2]), "r"(a[3]), "r"(b0), "r"(b1));
}

// ---------------- K0: zero the atomic accumulators ---------------------------
__global__ void zero_kernel(){
  int i = blockIdx.x*blockDim.x + threadIdx.x;
  if (i < BATCH*OUTF){ g_fvout[i] = 0.f; g_gates[i] = 0.f; }
  if (i < BATCH*KCL){ g_colnorm[i] = 0.f; g_asum[i] = 0.f; }
  if (i < KCL){ g_colsum[i] = 0.f; g_colsumsq[i] = 0.f; }
  if (i < BATCH) g_norm2[i] = 0.f;
}

// ---------------- K1: act_raw = X @ Wc  (+ column sum / sumsq for BN1) ------
__global__ __launch_bounds__(256) void gemm_act_kernel(
    const float* __restrict__ x, const float* __restrict__ wc){
  __shared__ float As[64][33];
  __shared__ float Bs[32][64];
  __shared__ float sSum[KCL], sSq[KCL];
  int tid = threadIdx.x;
  int row0 = blockIdx.x * 64;
  int tx = tid & 15, ty = tid >> 4;
  ull acc[4][2];
  #pragma unroll
  for (int i=0;i<4;i++){ acc[i][0]=0ull; acc[i][1]=0ull; }
  if (tid < KCL){ sSum[tid]=0.f; sSq[tid]=0.f; }

  for (int d0=0; d0<DIM; d0+=32){
    #pragma unroll
    for (int l=tid; l<2048; l+=256){
      int r=l>>5, c=l&31;
      As[r][c] = x[(row0+r)*DIM + d0 + c];
    }
    #pragma unroll
    for (int l=tid; l<2048; l+=256){
      int r=l>>6, c=l&63;
      Bs[r][c] = wc[(d0+r)*KCL + c];
    }
    __syncthreads();
    #pragma unroll
    for (int dd=0; dd<32; dd++){
      const ull* bp = reinterpret_cast<const ull*>(&Bs[dd][tx*4]);
      ull b0 = bp[0], b1 = bp[1];
      #pragma unroll
      for (int i=0;i<4;i++){
        float a = As[ty*4+i][dd];
        ull ap = pack2(a, a);
        ffma2(acc[i][0], ap, b0);
        ffma2(acc[i][1], ap, b1);
      }
    }
    __syncthreads();
  }
  float ps[4]={0,0,0,0}, pq[4]={0,0,0,0};
  #pragma unroll
  for (int i=0;i<4;i++){
    float v0=lo32(acc[i][0]), v1=hi32(acc[i][0]);
    float v2=lo32(acc[i][1]), v3=hi32(acc[i][1]);
    *reinterpret_cast<float4*>(&g_act[(row0+ty*4+i)*KCL + tx*4]) =
        make_float4(v0,v1,v2,v3);
    ps[0]+=v0; ps[1]+=v1; ps[2]+=v2; ps[3]+=v3;
    pq[0]+=v0*v0; pq[1]+=v1*v1; pq[2]+=v2*v2; pq[3]+=v3*v3;
  }
  #pragma unroll
  for (int j=0;j<4;j++){
    atomicAdd(&sSum[tx*4+j], ps[j]);
    atomicAdd(&sSq [tx*4+j], pq[j]);
  }
  __syncthreads();
  if (tid < KCL){
    atomicAdd(&g_colsum[tid],   sSum[tid]);
    atomicAdd(&g_colsumsq[tid], sSq[tid]);
  }
}

// ---------------- K2: BN1 + softmax (warp per row) + fused a_sum ------------
__global__ __launch_bounds__(256) void bn_softmax_kernel(
    const float* __restrict__ gamma, const float* __restrict__ beta){
  __shared__ float sbuf[8][KCL];
  int tid = threadIdx.x;
  int w = tid >> 5, lane = tid & 31;
  int row = blockIdx.x*8 + w;
  int b = row >> 9;
  const float inv_n = 1.f / (float)NROWS;
  int k2 = 2*lane;
  float2 cs = *reinterpret_cast<const float2*>(&g_colsum[k2]);
  float2 cq = *reinterpret_cast<const float2*>(&g_colsumsq[k2]);
  float2 ga = *reinterpret_cast<const float2*>(&gamma[k2]);
  float2 be = *reinterpret_cast<const float2*>(&beta[k2]);
  float m0 = cs.x*inv_n, m1 = cs.y*inv_n;
  float sc0 = ga.x*rsqrtf(cq.x*inv_n - m0*m0 + 1e-5f);
  float sc1 = ga.y*rsqrtf(cq.y*inv_n - m1*m1 + 1e-5f);
  float sh0 = be.x - m0*sc0, sh1 = be.y - m1*sc1;

  float2 v = *reinterpret_cast<const float2*>(&g_act[row*KCL + k2]);
  float vn0 = v.x*sc0 + sh0, vn1 = v.y*sc1 + sh1;
  float mx = fmaxf(vn0, vn1);
  #pragma unroll
  for (int o=16;o>0;o>>=1) mx = fmaxf(mx, __shfl_xor_sync(0xffffffffu, mx, o));
  float e0 = __expf(vn0 - mx), e1 = __expf(vn1 - mx);
  float s = e0 + e1;
  #pragma unroll
  for (int o=16;o>0;o>>=1) s += __shfl_xor_sync(0xffffffffu, s, o);
  float inv = 1.f / s;
  float p0 = e0*inv, p1 = e1*inv;
  *reinterpret_cast<float2*>(&g_act[row*KCL + k2]) = make_float2(p0, p1);
  *reinterpret_cast<float2*>(&sbuf[w][k2]) = make_float2(p0, p1);
  __syncthreads();
  if (tid < KCL){
    float t = 0.f;
    #pragma unroll
    for (int i=0;i<8;i++) t += sbuf[i][tid];
    atomicAdd(&g_asum[b*KCL + tid], t);
  }
}

// ---------------- K4: einsum + fused covariance transform + norm partials ---
__global__ __launch_bounds__(128) void einsum_kernel(
    const float* __restrict__ x,
    const float* __restrict__ covw, const float* __restrict__ cw2w){
  __shared__ float xs[32][64];
  __shared__ float as_[32][64];
  __shared__ float sCol[KCL];
  __shared__ float swp[4];
  int tid = threadIdx.x;
  int b = blockIdx.y, dt0 = blockIdx.x*64;
  int kg = tid & 15, dg = tid >> 4;      // 16 x 8
  int k0 = kg*4, d0 = dg*8;
  ull f1[4][4], f2[4][4];                // [k][d-ull pair]
  #pragma unroll
  for (int kk=0;kk<4;kk++)
    #pragma unroll
    for (int j=0;j<4;j++){ f1[kk][j]=0ull; f2[kk][j]=0ull; }

  for (int n0=0; n0<NPTS; n0+=32){
    #pragma unroll
    for (int l=tid; l<512; l+=128){
      int r = l>>4, c = (l&15)*4;
      *reinterpret_cast<float4*>(&xs[r][c]) =
          *reinterpret_cast<const float4*>(&x[(b*NPTS + n0 + r)*DIM + dt0 + c]);
      *reinterpret_cast<float4*>(&as_[r][c]) =
          *reinterpret_cast<const float4*>(&g_act[(b*NPTS + n0 + r)*KCL + c]);
    }
    __syncthreads();
    #pragma unroll
    for (int nn=0; nn<32; nn++){
      const ull* xp = reinterpret_cast<const ull*>(&xs[nn][d0]);
      ull xv[4], qv[4];
      #pragma unroll
      for (int j=0;j<4;j++){ xv[j] = xp[j]; qv[j] = mul2(xv[j], xv[j]); }
      float4 av = *reinterpret_cast<const float4*>(&as_[nn][k0]);
      ull a0 = pack2(av.x, av.x), a1 = pack2(av.y, av.y);
      ull a2 = pack2(av.z, av.z), a3 = pack2(av.w, av.w);
      #pragma unroll
      for (int j=0;j<4;j++){
        ffma2(f1[0][j], xv[j], a0); ffma2(f1[1][j], xv[j], a1);
        ffma2(f1[2][j], xv[j], a2); ffma2(f1[3][j], xv[j], a3);
        ffma2(f2[0][j], qv[j], a0); ffma2(f2[1][j], qv[j], a1);
        ffma2(f2[2][j], qv[j], a2); ffma2(f2[3][j], qv[j], a3);
      }
    }
    __syncthreads();
  }

  // ---- fused transform epilogue ----
  float4 asv = *reinterpret_cast<const float4*>(&g_asum[b*KCL + k0]);
  float asm_[4] = {asv.x, asv.y, asv.z, asv.w};
  float pcol[4] = {0.f,0.f,0.f,0.f};
  float pn2 = 0.f;
  #pragma unroll
  for (int j=0;j<4;j++){
    int dbase = dt0 + d0 + j*2;
    #pragma unroll
    for (int h=0; h<2; h++){
      int dd = dbase + h;
      float4 cw = *reinterpret_cast<const float4*>(&cw2w[dd*KCL + k0]);
      float4 cv = *reinterpret_cast<const float4*>(&covw[dd*KCL + k0]);
      float f1v[4], f2v[4];
      #pragma unroll
      for (int m=0;m<4;m++){
        f1v[m] = h ? hi32(f1[m][j]) : lo32(f1[m][j]);
        f2v[m] = h ? hi32(f2[m][j]) : lo32(f2[m][j]);
      }
      float o1[4], o2[4];
      const float* cwp = &cw.x;
      const float* cvp = &cv.x;
      #pragma unroll
      for (int m=0;m<4;m++){
        float cwm = cwp[m], cvm = cvp[m];
        float cwv = cvm*cvm + 1e-6f;
        float rc = __fdividef(1.f, cwv);
        float f1t = (f1v[m] - asm_[m]*cwm) * rc;
        float f2t = (asm_[m]*cwm*cwm + f2v[m] - 2.f*f1v[m]*cwm) * rc * rc - asm_[m];
        o1[m] = f1t; o2[m] = f2t;
        pcol[m] += f1t*f1t; pn2 += f2t*f2t;
      }
      *reinterpret_cast<float4*>(&g_fv1[(b*DIM + dd)*KCL + k0]) =
          make_float4(o1[0],o1[1],o1[2],o1[3]);
      *reinterpret_cast<float4*>(&g_fv2[(b*DIM + dd)*KCL + k0]) =
          make_float4(o2[0],o2[1],o2[2],o2[3]);
    }
  }
  if (tid < KCL) sCol[tid] = 0.f;
  __syncthreads();
  #pragma unroll
  for (int m=0;m<4;m++) atomicAdd(&sCol[k0+m], pcol[m]);
  #pragma unroll
  for (int o=16;o>0;o>>=1) pn2 += __shfl_xor_sync(0xffffffffu, pn2, o);
  if ((tid&31)==0) swp[tid>>5] = pn2;
  __syncthreads();
  if (tid < KCL) atomicAdd(&g_colnorm[b*KCL + tid], sCol[tid]);
  if (tid == 0)
    atomicAdd(&g_norm2[b], swp[0]+swp[1]+swp[2]+swp[3]);
}

// ---------------- K5b: tiny — fold the two-stage norms into scale tables ----
__global__ __launch_bounds__(64) void scale_kernel(){
  int b = blockIdx.x, k = threadIdx.x;
  float cn = g_colnorm[b*KCL + k];
  float inv1 = 1.f / fmaxf(sqrtf(cn), 1e-12f);
  float contrib = cn * inv1 * inv1;
  float t = contrib;
  #pragma unroll
  for (int o=16;o>0;o>>=1) t += __shfl_xor_sync(0xffffffffu, t, o);
  __shared__ float sw[2];
  if ((k&31)==0) sw[k>>5] = t;
  __syncthreads();
  float n1 = sqrtf(sw[0] + sw[1]);
  g_scale1[b*KCL + k] = inv1 / fmaxf(n1, 1e-12f);
  if (k == 0) g_scale2[b] = 1.f / fmaxf(sqrtf(g_norm2[b]), 1e-12f);
}

// ---------------- K6: hidden1 via bf16 tensor cores (split emulation) -------
// out[32,1024] += A[32,2048-chunk] @ W[chunk,1024]
// A = g_fv1 (scaled by scale1) or g_fv2 (scaled by scale2), split into
// bf16 hi (exact truncation) + bf16 lo; W split per-thread the same way.
// 3 mma terms: AhWh + AlWh + AhWl (AlWl ~2^-16, dropped).
// grid (4 o-tiles of 256, 64 k-chunks of 2048), block 256 = 8 warps.
// Warp w owns n-cols [w*32, w*32+32) of the o-tile; m = all 32 batches.
// W fragments load straight from GMEM (one consumer per element).
__global__ __launch_bounds__(256, 2) void gemm_fc1_hmma(
    const float* __restrict__ W){
  __shared__ uint AhS[2][32][12];   // [buf][batch][k-pair] (12 pad, 8 used)
  __shared__ uint AlS[2][32][12];
  __shared__ float scl[BATCH*KCL];
  int tid = threadIdx.x;
  int warp = tid >> 5, lane = tid & 31;
  int i0 = blockIdx.y * 2048;
  int o0 = blockIdx.x * 256;

  const float* A;
  int iA0, half1;
  if (i0 < HALF1){ A = g_fv1; iA0 = i0; half1 = 1;
    for (int l = tid; l < BATCH*KCL; l += 256) scl[l] = g_scale1[l];
  } else { A = g_fv2; iA0 = i0 - HALF1; half1 = 0; }

  // A staging role
  int bA = tid >> 3;            // batch 0..31
  int qA = tid & 7;             // k-pair 0..7
  float sc2b = half1 ? 1.f : g_scale2[bA];
  __syncthreads();              // scl visible

  // W fragment base: n column this thread owns, k row offset
  int ncol = o0 + warp*32 + (lane >> 2);
  int krow = 2*(lane & 3);

  float acc[2][4][4];
  #pragma unroll
  for (int mt=0;mt<2;mt++)
    #pragma unroll
    for (int nt=0;nt<4;nt++)
      #pragma unroll
      for (int c=0;c<4;c++) acc[mt][nt][c] = 0.f;

  // ---- stage A step 0 into buf 0 ----
  {
    int iAt = iA0;
    float2 av = *reinterpret_cast<const float2*>(&A[bA*HALF1 + iAt + 2*qA]);
    float s0, s1;
    if (half1){ int kk = (iAt + 2*qA) & 63; s0 = scl[bA*KCL+kk]; s1 = scl[bA*KCL+kk+1]; }
    else { s0 = sc2b; s1 = sc2b; }
    float v0 = av.x*s0, v1 = av.y*s1;
    AhS[0][bA][qA] = prmt_hi(v0, v1);
    AlS[0][bA][qA] = cvt_bf2(v1 - trunc_bf(v1), v0 - trunc_bf(v0));
  }
  // ---- preload W step 0 ----
  float wcur[16];
  {
    const float* wp = W + (size_t)(i0 + krow)*OUTF + ncol;
    #pragma unroll
    for (int nt=0;nt<4;nt++){
      wcur[nt*4+0] = wp[nt*8];
      wcur[nt*4+1] = wp[nt*8 + OUTF];
      wcur[nt*4+2] = wp[nt*8 + 8*OUTF];
      wcur[nt*4+3] = wp[nt*8 + 9*OUTF];
    }
  }
  __syncthreads();

  const int T = 2048/16;   // 128 k16 steps
  for (int t=0; t<T; t++){
    int cur = t & 1;
    bool more = (t+1) < T;
    // prefetch next W + next A
    float wnxt[16]; float2 av; float s0=1.f, s1=1.f;
    if (more){
      const float* wp = W + (size_t)(i0 + (t+1)*16 + krow)*OUTF + ncol;
      #pragma unroll
      for (int nt=0;nt<4;nt++){
        wnxt[nt*4+0] = wp[nt*8];
        wnxt[nt*4+1] = wp[nt*8 + OUTF];
        wnxt[nt*4+2] = wp[nt*8 + 8*OUTF];
        wnxt[nt*4+3] = wp[nt*8 + 9*OUTF];
      }
      int iAt = iA0 + (t+1)*16;
      av = *reinterpret_cast<const float2*>(&A[bA*HALF1 + iAt + 2*qA]);
      if (half1){ int kk = (iAt + 2*qA) & 63; s0 = scl[bA*KCL+kk]; s1 = scl[bA*KCL+kk+1]; }
      else { s0 = sc2b; s1 = sc2b; }
    }
    // A fragments from smem
    uint ah[8], al[8];
    #pragma unroll
    for (int mt=0;mt<2;mt++){
      int r = (lane>>2) + mt*16;
      int c = lane & 3;
      ah[mt*4+0] = AhS[cur][r  ][c];
      ah[mt*4+1] = AhS[cur][r+8][c];
      ah[mt*4+2] = AhS[cur][r  ][c+4];
      ah[mt*4+3] = AhS[cur][r+8][c+4];
      al[mt*4+0] = AlS[cur][r  ][c];
      al[mt*4+1] = AlS[cur][r+8][c];
      al[mt*4+2] = AlS[cur][r  ][c+4];
      al[mt*4+3] = AlS[cur][r+8][c+4];
    }
    // split current W
    uint whi[8], wlo[8];
    #pragma unroll
    for (int nt=0;nt<4;nt++){
      float w0 = wcur[nt*4+0], w1 = wcur[nt*4+1];
      float w2 = wcur[nt*4+2], w3 = wcur[nt*4+3];
      whi[nt*2+0] = prmt_hi(w0, w1);
      whi[nt*2+1] = prmt_hi(w2, w3);
      wlo[nt*2+0] = cvt_bf2(w1 - trunc_bf(w1), w0 - trunc_bf(w0));
      wlo[nt*2+1] = cvt_bf2(w3 - trunc_bf(w3), w2 - trunc_bf(w2));
    }
    // 24 mma
    #pragma unroll
    for (int mt=0;mt<2;mt++){
      #pragma unroll
      for (int nt=0;nt<4;nt++){
        mma_bf16(acc[mt][nt], &ah[mt*4], whi[nt*2], whi[nt*2+1]);
        mma_bf16(acc[mt][nt], &al[mt*4], whi[nt*2], whi[nt*2+1]);
        mma_bf16(acc[mt][nt], &ah[mt*4], wlo[nt*2], wlo[nt*2+1]);
      }
    }
    // stash next A
    if (more){
      float v0 = av.x*s0, v1 = av.y*s1;
      AhS[cur^1][bA][qA] = prmt_hi(v0, v1);
      AlS[cur^1][bA][qA] = cvt_bf2(v1 - trunc_bf(v1), v0 - trunc_bf(v0));
      #pragma unroll
      for (int p=0;p<16;p++) wcur[p] = wnxt[p];
    }
    __syncthreads();
  }

  // epilogue: atomic accumulate
  #pragma unroll
  for (int mt=0;mt<2;mt++)
    #pragma unroll
    for (int nt=0;nt<4;nt++)
      #pragma unroll
      for (int c=0;c<4;c++){
        int row = (lane>>2) + ((c>=2)?8:0) + mt*16;
        int col = o0 + warp*32 + nt*8 + 2*(lane&3) + (c&1);
        atomicAdd(&g_fvout[row*OUTF + col], acc[mt][nt][c]);
      }
}

// ---------------- K7a: gating GEMM (fp32 FFMA2, small) ----------------------
#define FC_KT 16
__global__ __launch_bounds__(256) void gemm_fc_kernel(
    const float* __restrict__ W, int ichunk){
  __shared__ float Ws[2][FC_KT][256];
  __shared__ float fs[2][FC_KT][32];
  int tid = threadIdx.x;
  int o0 = blockIdx.x * 256;
  int i0 = blockIdx.y * ichunk;
  int og = tid & 63, bg = tid >> 6;
  const float* A = g_fvout; float* out = g_gates;
  int bload = tid & 31;
  int rload0 = (tid >> 5)*2;

  int T = ichunk / FC_KT;
  int roff[4], coff[4];
  #pragma unroll
  for (int p=0;p<4;p++){
    int off = p*1024 + tid*4;
    roff[p] = off >> 8; coff[p] = off & 255;
  }

  ull acc[8][2];
  #pragma unroll
  for (int bb=0;bb<8;bb++){ acc[bb][0]=0ull; acc[bb][1]=0ull; }

  float4 pw[4]; float pa0, pa1;
  {
    #pragma unroll
    for (int p=0;p<4;p++)
      pw[p] = *reinterpret_cast<const float4*>(&W[(i0+roff[p])*OUTF + o0 + coff[p]]);
    pa0 = A[bload*OUTF + i0 + rload0];
    pa1 = A[bload*OUTF + i0 + rload0 + 1];
  }
  #pragma unroll
  for (int p=0;p<4;p++)
    *reinterpret_cast<float4*>(&Ws[0][roff[p]][coff[p]]) = pw[p];
  fs[0][rload0][bload] = pa0;
  fs[0][rload0+1][bload] = pa1;
  __syncthreads();

  for (int t=0; t<T; t++){
    int cur = t & 1;
    bool more = (t+1) < T;
    if (more){
      int i  = i0 + (t+1)*FC_KT;
      #pragma unroll
      for (int p=0;p<4;p++)
        pw[p] = *reinterpret_cast<const float4*>(&W[(i+roff[p])*OUTF + o0 + coff[p]]);
      pa0 = A[bload*OUTF + i + rload0];
      pa1 = A[bload*OUTF + i + rload0 + 1];
    }
    #pragma unroll
    for (int ii=0; ii<FC_KT; ii++){
      const ull* wp = reinterpret_cast<const ull*>(&Ws[cur][ii][og*4]);
      ull w0 = wp[0], w1 = wp[1];
      float4 fa = *reinterpret_cast<const float4*>(&fs[cur][ii][bg*8]);
      float4 fb = *reinterpret_cast<const float4*>(&fs[cur][ii][bg*8+4]);
      ull a0 = pack2(fa.x,fa.x), a1 = pack2(fa.y,fa.y);
      ull a2 = pack2(fa.z,fa.z), a3 = pack2(fa.w,fa.w);
      ull a4 = pack2(fb.x,fb.x), a5 = pack2(fb.y,fb.y);
      ull a6 = pack2(fb.z,fb.z), a7 = pack2(fb.w,fb.w);
      ffma2(acc[0][0], a0, w0); ffma2(acc[0][1], a0, w1);
      ffma2(acc[1][0], a1, w0); ffma2(acc[1][1], a1, w1);
      ffma2(acc[2][0], a2, w0); ffma2(acc[2][1], a2, w1);
      ffma2(acc[3][0], a3, w0); ffma2(acc[3][1], a3, w1);
      ffma2(acc[4][0], a4, w0); ffma2(acc[4][1], a4, w1);
      ffma2(acc[5][0], a5, w0); ffma2(acc[5][1], a5, w1);
      ffma2(acc[6][0], a6, w0); ffma2(acc[6][1], a6, w1);
      ffma2(acc[7][0], a7, w0); ffma2(acc[7][1], a7, w1);
    }
    if (more){
      int nxt = (t+1) & 1;
      #pragma unroll
      for (int p=0;p<4;p++)
        *reinterpret_cast<float4*>(&Ws[nxt][roff[p]][coff[p]]) = pw[p];
      fs[nxt][rload0][bload] = pa0;
      fs[nxt][rload0+1][bload] = pa1;
    }
    __syncthreads();
  }

  #pragma unroll
  for (int bb=0;bb<8;bb++){
    int b = bg*8 + bb;
    #pragma unroll
    for (int t=0;t<2;t++){
      int base = b*OUTF + o0 + og*4 + t*2;
      atomicAdd(&out[base],   lo32(acc[bb][t]));
      atomicAdd(&out[base+1], hi32(acc[bb][t]));
    }
  }
}

// ---------------- K7b: BN2 (batch stats over 32) + sigmoid gate -------------
__global__ __launch_bounds__(256) void bn2_gate_kernel(
    const float* __restrict__ g2, const float* __restrict__ b2,
    float* __restrict__ out){
  int o = blockIdx.x*blockDim.x + threadIdx.x;   // 0..1023
  float m=0.f, s=0.f;
  #pragma unroll 8
  for (int b=0;b<BATCH;b++){ float v = g_gates[b*OUTF + o]; m += v; s += v*v; }
  m *= (1.f/BATCH);
  float var = s*(1.f/BATCH) - m*m;
  float rs = rsqrtf(var + 1e-5f);
  float ga = g2[o], be = b2[o];
  #pragma unroll 8
  for (int b=0;b<BATCH;b++){
    float v = (g_gates[b*OUTF + o] - m)*rs*ga + be;
    float sig = 1.f/(1.f + expf(-v));
    out[b*OUTF + o] = g_fvout[b*OUTF + o] * sig;
  }
}

// ---------------------------------------------------------------------------
extern "C" void kernel_launch(void* const* d_in, const int* in_sizes, int n_in,
                              void* d_out, int out_size){
  const float* x   = (const float*)d_in[0];   // [32,512,1024]
  const float* wc  = (const float*)d_in[1];   // [1024,64]
  const float* cov = (const float*)d_in[2];   // [1024,64]
  const float* cw2 = (const float*)d_in[3];   // [1,1024,64]
  const float* w1  = (const float*)d_in[4];   // [131072,1024]
  const float* g1  = (const float*)d_in[5];   // [64]
  const float* b1  = (const float*)d_in[6];   // [64]
  const float* wg  = (const float*)d_in[7];   // [1024,1024]
  const float* g2  = (const float*)d_in[8];   // [1024]
  const float* b2  = (const float*)d_in[9];   // [1024]
  float* out = (float*)d_out;                 // [32,1024]

  zero_kernel<<<128, 256>>>();
  gemm_act_kernel<<<256, 256>>>(x, wc);
  bn_softmax_kernel<<<2048, 256>>>(g1, b1);
  einsum_kernel<<<dim3(16, 32), 128>>>(x, cov, cw2);
  scale_kernel<<<BATCH, 64>>>();
  gemm_fc1_hmma<<<dim3(4, 64), 256>>>(w1);           // hidden1 (tensor cores)
  gemm_fc_kernel<<<dim3(4, 8), 256>>>(wg, 128);      // gating (fp32)
  bn2_gate_kernel<<<4, 256>>>(g2, b2, out);
}

// round 11
// speedup vs baseline: 1.8150x; 1.1042x over previous
#include <cuda_runtime.h>

#define BATCH 32
#define NPTS 512
#define DIM 1024
#define KCL 64
#define NROWS (BATCH*NPTS)      /* 16384 */
#define OUTF 1024
#define IN2 (2*DIM*KCL)         /* 131072 */
#define HALF1 (DIM*KCL)         /* 65536 */

// ---------------- scratch (device globals: no allocations allowed) ----------
__device__ float g_act[NROWS*KCL];          // 4 MB
__device__ float g_colsum[KCL];
__device__ float g_colsumsq[KCL];
__device__ float g_asum[BATCH*KCL];
__device__ float g_fv1[BATCH*DIM*KCL];      // 8 MB
__device__ float g_fv2[BATCH*DIM*KCL];      // 8 MB
__device__ float g_colnorm[BATCH*KCL];
__device__ float g_norm2[BATCH];
__device__ float g_scale1[BATCH*KCL];
__device__ float g_scale2[BATCH];
__device__ float g_fvout[BATCH*OUTF];
__device__ float g_gates[BATCH*OUTF];

typedef unsigned long long ull;
typedef unsigned int uint;

// ---------------- f32x2 helpers (FFMA2: 2 FMAs / instr on sm_103a) ----------
__device__ __forceinline__ ull pack2(float lo, float hi){
  ull r;
  asm("mov.b64 %0, {%1, %2};" : "=l"(r)
      : "r"(__float_as_uint(lo)), "r"(__float_as_uint(hi)));
  return r;
}
__device__ __forceinline__ void ffma2(ull &d, ull a, ull b){
  asm("fma.rn.f32x2 %0, %1, %2, %3;" : "=l"(d) : "l"(a), "l"(b), "l"(d));
}
__device__ __forceinline__ float lo32(ull v){ return __uint_as_float((unsigned)(v & 0xffffffffull)); }
__device__ __forceinline__ float hi32(ull v){ return __uint_as_float((unsigned)(v >> 32)); }

// ---------------- bf16 split helpers ----------------------------------------
// hi-pack: lower16(result)=top16(a), upper16(result)=top16(b) -- exact trunc
__device__ __forceinline__ uint prmt_hi(float a, float b){
  uint r;
  asm("prmt.b32 %0, %1, %2, 0x7632;" : "=r"(r)
      : "r"(__float_as_uint(a)), "r"(__float_as_uint(b)));
  return r;
}
__device__ __forceinline__ float trunc_bf(float v){
  return __uint_as_float(__float_as_uint(v) & 0xffff0000u);
}
__device__ __forceinline__ uint cvt_bf2(float upper, float lower){
  uint r;
  asm("cvt.rn.bf16x2.f32 %0, %1, %2;" : "=r"(r) : "f"(upper), "f"(lower));
  return r;
}
__device__ __forceinline__ void mma_bf16(float* c, const uint* a, uint b0, uint b1){
  asm volatile(
    "mma.sync.aligned.m16n8k16.row.col.f32.bf16.bf16.f32 "
    "{%0,%1,%2,%3},{%4,%5,%6,%7},{%8,%9},{%0,%1,%2,%3};"
    : "+f"(c[0]), "+f"(c[1]), "+f"(c[2]), "+f"(c[3])
    : "r"(a[0]), "r"(a[1]), "r"(a[2]), "r"(a[3]), "r"(b0), "r"(b1));
}

// ---------------- K0: zero the atomic accumulators ---------------------------
__global__ void zero_kernel(){
  int i = blockIdx.x*blockDim.x + threadIdx.x;
  if (i < BATCH*OUTF){ g_fvout[i] = 0.f; g_gates[i] = 0.f; }
  if (i < BATCH*KCL){ g_colnorm[i] = 0.f; g_asum[i] = 0.f; }
  if (i < KCL){ g_colsum[i] = 0.f; g_colsumsq[i] = 0.f; }
  if (i < BATCH) g_norm2[i] = 0.f;
}

// ---------------- K1: act_raw = X @ Wc  (+ column sum / sumsq for BN1) ------
__global__ __launch_bounds__(256) void gemm_act_kernel(
    const float* __restrict__ x, const float* __restrict__ wc){
  __shared__ float As[64][33];
  __shared__ float Bs[32][64];
  __shared__ float sSum[KCL], sSq[KCL];
  int tid = threadIdx.x;
  int row0 = blockIdx.x * 64;
  int tx = tid & 15, ty = tid >> 4;
  ull acc[4][2];
  #pragma unroll
  for (int i=0;i<4;i++){ acc[i][0]=0ull; acc[i][1]=0ull; }
  if (tid < KCL){ sSum[tid]=0.f; sSq[tid]=0.f; }

  for (int d0=0; d0<DIM; d0+=32){
    #pragma unroll
    for (int l=tid; l<2048; l+=256){
      int r=l>>5, c=l&31;
      As[r][c] = x[(row0+r)*DIM + d0 + c];
    }
    #pragma unroll
    for (int l=tid; l<2048; l+=256){
      int r=l>>6, c=l&63;
      Bs[r][c] = wc[(d0+r)*KCL + c];
    }
    __syncthreads();
    #pragma unroll
    for (int dd=0; dd<32; dd++){
      const ull* bp = reinterpret_cast<const ull*>(&Bs[dd][tx*4]);
      ull b0 = bp[0], b1 = bp[1];
      #pragma unroll
      for (int i=0;i<4;i++){
        float a = As[ty*4+i][dd];
        ull ap = pack2(a, a);
        ffma2(acc[i][0], ap, b0);
        ffma2(acc[i][1], ap, b1);
      }
    }
    __syncthreads();
  }
  float ps[4]={0,0,0,0}, pq[4]={0,0,0,0};
  #pragma unroll
  for (int i=0;i<4;i++){
    float v0=lo32(acc[i][0]), v1=hi32(acc[i][0]);
    float v2=lo32(acc[i][1]), v3=hi32(acc[i][1]);
    *reinterpret_cast<float4*>(&g_act[(row0+ty*4+i)*KCL + tx*4]) =
        make_float4(v0,v1,v2,v3);
    ps[0]+=v0; ps[1]+=v1; ps[2]+=v2; ps[3]+=v3;
    pq[0]+=v0*v0; pq[1]+=v1*v1; pq[2]+=v2*v2; pq[3]+=v3*v3;
  }
  #pragma unroll
  for (int j=0;j<4;j++){
    atomicAdd(&sSum[tx*4+j], ps[j]);
    atomicAdd(&sSq [tx*4+j], pq[j]);
  }
  __syncthreads();
  if (tid < KCL){
    atomicAdd(&g_colsum[tid],   sSum[tid]);
    atomicAdd(&g_colsumsq[tid], sSq[tid]);
  }
}

// ---------------- K2: BN1 + softmax (warp per row) + fused a_sum ------------
__global__ __launch_bounds__(256) void bn_softmax_kernel(
    const float* __restrict__ gamma, const float* __restrict__ beta){
  __shared__ float sbuf[8][KCL];
  int tid = threadIdx.x;
  int w = tid >> 5, lane = tid & 31;
  int row = blockIdx.x*8 + w;
  int b = row >> 9;
  const float inv_n = 1.f / (float)NROWS;
  int k2 = 2*lane;
  float2 cs = *reinterpret_cast<const float2*>(&g_colsum[k2]);
  float2 cq = *reinterpret_cast<const float2*>(&g_colsumsq[k2]);
  float2 ga = *reinterpret_cast<const float2*>(&gamma[k2]);
  float2 be = *reinterpret_cast<const float2*>(&beta[k2]);
  float m0 = cs.x*inv_n, m1 = cs.y*inv_n;
  float sc0 = ga.x*rsqrtf(cq.x*inv_n - m0*m0 + 1e-5f);
  float sc1 = ga.y*rsqrtf(cq.y*inv_n - m1*m1 + 1e-5f);
  float sh0 = be.x - m0*sc0, sh1 = be.y - m1*sc1;

  float2 v = *reinterpret_cast<const float2*>(&g_act[row*KCL + k2]);
  float vn0 = v.x*sc0 + sh0, vn1 = v.y*sc1 + sh1;
  float mx = fmaxf(vn0, vn1);
  #pragma unroll
  for (int o=16;o>0;o>>=1) mx = fmaxf(mx, __shfl_xor_sync(0xffffffffu, mx, o));
  float e0 = __expf(vn0 - mx), e1 = __expf(vn1 - mx);
  float s = e0 + e1;
  #pragma unroll
  for (int o=16;o>0;o>>=1) s += __shfl_xor_sync(0xffffffffu, s, o);
  float inv = 1.f / s;
  float p0 = e0*inv, p1 = e1*inv;
  *reinterpret_cast<float2*>(&g_act[row*KCL + k2]) = make_float2(p0, p1);
  *reinterpret_cast<float2*>(&sbuf[w][k2]) = make_float2(p0, p1);
  __syncthreads();
  if (tid < KCL){
    float t = 0.f;
    #pragma unroll
    for (int i=0;i<8;i++) t += sbuf[i][tid];
    atomicAdd(&g_asum[b*KCL + tid], t);
  }
}

// ---------------- K4: einsum via bf16 tensor cores + fused transform --------
// Per block: b, d-tile of 64. C1[64k x 64d] = act^T @ X ; C2 = act^T @ X^2.
// Split bf16 scheme (same as FC1): 3 mma terms per product.
// 256 threads = 8 warps: warp m-half (wm=warp&1: 32 k-rows), n-quarter
// (wn=warp>>2... warp>>1: 16 d-cols). 32 n-steps of 16, double-buffered smem.
__global__ __launch_bounds__(256, 2) void einsum_tc_kernel(
    const float* __restrict__ x,
    const float* __restrict__ covw, const float* __restrict__ cw2w){
  __shared__ uint aTh[2][64][12];   // [buf][kcl][npair] (8 used, pad 12)
  __shared__ uint aTl[2][64][12];
  __shared__ uint xh[2][8][72];     // [buf][npair][d64] (pad 72)
  __shared__ uint xl[2][8][72];
  __shared__ uint qh[2][8][72];
  __shared__ uint ql[2][8][72];
  __shared__ float sAsum[KCL];
  __shared__ float sCol[KCL];
  __shared__ float swp[8];
  int tid = threadIdx.x, warp = tid >> 5, lane = tid & 31;
  int b = blockIdx.y, d0 = blockIdx.x * 64;
  int wm = warp & 1, wn = warp >> 1;
  // staging roles
  int px  = tid >> 5;            // x: n-pair 0..7
  int dcx = (tid & 31) * 2;      // x: 2 d-cols
  int ka  = tid & 63;            // a: k row
  int pa  = (tid >> 6) * 2;      // a: 2 n-pairs
  if (tid < KCL){ sAsum[tid] = g_asum[b*KCL + tid]; sCol[tid] = 0.f; }

  float acc1[2][2][4], acc2[2][2][4];
  #pragma unroll
  for (int mt=0;mt<2;mt++)
    #pragma unroll
    for (int nt=0;nt<2;nt++)
      #pragma unroll
      for (int c=0;c<4;c++){ acc1[mt][nt][c]=0.f; acc2[mt][nt][c]=0.f; }

  const float* xrow = x + (size_t)b*NPTS*DIM + d0;
  const float* arow = g_act + (size_t)b*NPTS*KCL;

  // prefetch step 0
  float xv[4], av[4];
  {
    float2 t0 = *reinterpret_cast<const float2*>(&xrow[(2*px  )*DIM + dcx]);
    float2 t1 = *reinterpret_cast<const float2*>(&xrow[(2*px+1)*DIM + dcx]);
    xv[0]=t0.x; xv[1]=t0.y; xv[2]=t1.x; xv[3]=t1.y;
    #pragma unroll
    for (int j=0;j<4;j++) av[j] = arow[(2*pa+j)*KCL + ka];
  }
  // stage buf 0
  {
    float q0=xv[0]*xv[0], q1=xv[1]*xv[1], q2=xv[2]*xv[2], q3=xv[3]*xv[3];
    xh[0][px][dcx  ] = prmt_hi(xv[0], xv[2]);
    xh[0][px][dcx+1] = prmt_hi(xv[1], xv[3]);
    xl[0][px][dcx  ] = cvt_bf2(xv[2]-trunc_bf(xv[2]), xv[0]-trunc_bf(xv[0]));
    xl[0][px][dcx+1] = cvt_bf2(xv[3]-trunc_bf(xv[3]), xv[1]-trunc_bf(xv[1]));
    qh[0][px][dcx  ] = prmt_hi(q0, q2);
    qh[0][px][dcx+1] = prmt_hi(q1, q3);
    ql[0][px][dcx  ] = cvt_bf2(q2-trunc_bf(q2), q0-trunc_bf(q0));
    ql[0][px][dcx+1] = cvt_bf2(q3-trunc_bf(q3), q1-trunc_bf(q1));
    aTh[0][ka][pa  ] = prmt_hi(av[0], av[1]);
    aTh[0][ka][pa+1] = prmt_hi(av[2], av[3]);
    aTl[0][ka][pa  ] = cvt_bf2(av[1]-trunc_bf(av[1]), av[0]-trunc_bf(av[0]));
    aTl[0][ka][pa+1] = cvt_bf2(av[3]-trunc_bf(av[3]), av[2]-trunc_bf(av[2]));
  }
  __syncthreads();

  int r = lane >> 2, cfr = lane & 3;     // fragment indices
  for (int t=0; t<32; t++){
    int cur = t & 1;
    bool more = (t+1) < 32;
    if (more){
      int n0 = (t+1)*16;
      float2 t0 = *reinterpret_cast<const float2*>(&xrow[(n0+2*px  )*DIM + dcx]);
      float2 t1 = *reinterpret_cast<const float2*>(&xrow[(n0+2*px+1)*DIM + dcx]);
      xv[0]=t0.x; xv[1]=t0.y; xv[2]=t1.x; xv[3]=t1.y;
      #pragma unroll
      for (int j=0;j<4;j++) av[j] = arow[(n0+2*pa+j)*KCL + ka];
    }
    // A fragments
    uint ah[2][4], al[2][4];
    #pragma unroll
    for (int mt=0;mt<2;mt++){
      int rb = wm*32 + mt*16;
      ah[mt][0]=aTh[cur][rb+r  ][cfr];   ah[mt][1]=aTh[cur][rb+r+8][cfr];
      ah[mt][2]=aTh[cur][rb+r  ][cfr+4]; ah[mt][3]=aTh[cur][rb+r+8][cfr+4];
      al[mt][0]=aTl[cur][rb+r  ][cfr];   al[mt][1]=aTl[cur][rb+r+8][cfr];
      al[mt][2]=aTl[cur][rb+r  ][cfr+4]; al[mt][3]=aTl[cur][rb+r+8][cfr+4];
    }
    // B fragments + mma
    #pragma unroll
    for (int nt=0;nt<2;nt++){
      int col = wn*16 + nt*8 + r;
      uint bxh0 = xh[cur][cfr][col], bxh1 = xh[cur][cfr+4][col];
      uint bxl0 = xl[cur][cfr][col], bxl1 = xl[cur][cfr+4][col];
      uint bqh0 = qh[cur][cfr][col], bqh1 = qh[cur][cfr+4][col];
      uint bql0 = ql[cur][cfr][col], bql1 = ql[cur][cfr+4][col];
      #pragma unroll
      for (int mt=0;mt<2;mt++){
        mma_bf16(acc1[mt][nt], ah[mt], bxh0, bxh1);
        mma_bf16(acc1[mt][nt], al[mt], bxh0, bxh1);
        mma_bf16(acc1[mt][nt], ah[mt], bxl0, bxl1);
        mma_bf16(acc2[mt][nt], ah[mt], bqh0, bqh1);
        mma_bf16(acc2[mt][nt], al[mt], bqh0, bqh1);
        mma_bf16(acc2[mt][nt], ah[mt], bql0, bql1);
      }
    }
    if (more){
      int nxt = cur ^ 1;
      float q0=xv[0]*xv[0], q1=xv[1]*xv[1], q2=xv[2]*xv[2], q3=xv[3]*xv[3];
      xh[nxt][px][dcx  ] = prmt_hi(xv[0], xv[2]);
      xh[nxt][px][dcx+1] = prmt_hi(xv[1], xv[3]);
      xl[nxt][px][dcx  ] = cvt_bf2(xv[2]-trunc_bf(xv[2]), xv[0]-trunc_bf(xv[0]));
      xl[nxt][px][dcx+1] = cvt_bf2(xv[3]-trunc_bf(xv[3]), xv[1]-trunc_bf(xv[1]));
      qh[nxt][px][dcx  ] = prmt_hi(q0, q2);
      qh[nxt][px][dcx+1] = prmt_hi(q1, q3);
      ql[nxt][px][dcx  ] = cvt_bf2(q2-trunc_bf(q2), q0-trunc_bf(q0));
      ql[nxt][px][dcx+1] = cvt_bf2(q3-trunc_bf(q3), q1-trunc_bf(q1));
      aTh[nxt][ka][pa  ] = prmt_hi(av[0], av[1]);
      aTh[nxt][ka][pa+1] = prmt_hi(av[2], av[3]);
      aTl[nxt][ka][pa  ] = cvt_bf2(av[1]-trunc_bf(av[1]), av[0]-trunc_bf(av[0]));
      aTl[nxt][ka][pa+1] = cvt_bf2(av[3]-trunc_bf(av[3]), av[2]-trunc_bf(av[2]));
    }
    __syncthreads();
  }

  // ---- fused transform epilogue + reductions ----
  float pn2 = 0.f;
  float pcol[2][2] = {{0.f,0.f},{0.f,0.f}};   // [mt][c>=2 half]
  #pragma unroll
  for (int mt=0;mt<2;mt++){
    #pragma unroll
    for (int nt=0;nt<2;nt++){
      #pragma unroll
      for (int c=0;c<4;c++){
        int k   = wm*32 + mt*16 + r + ((c>=2)?8:0);
        int dl  = wn*16 + nt*8 + 2*cfr + (c&1);
        int dgl = d0 + dl;
        int widx = dgl*KCL + k;
        float cwm = cw2w[widx];
        float cvm = covw[widx];
        float asum = sAsum[k];
        float cwv = cvm*cvm + 1e-6f;
        float rc = __fdividef(1.f, cwv);
        float f1r = acc1[mt][nt][c], f2r = acc2[mt][nt][c];
        float f1t = (f1r - asum*cwm) * rc;
        float f2t = (asum*cwm*cwm + f2r - 2.f*f1r*cwm) * rc * rc - asum;
        g_fv1[(b*DIM + dgl)*KCL + k] = f1t;
        g_fv2[(b*DIM + dgl)*KCL + k] = f2t;
        pcol[mt][c>>1 & 1] += f1t*f1t;
        pn2 += f2t*f2t;
      }
    }
  }
  #pragma unroll
  for (int mt=0;mt<2;mt++)
    #pragma unroll
    for (int h=0;h<2;h++){
      int k = wm*32 + mt*16 + r + h*8;
      atomicAdd(&sCol[k], pcol[mt][h]);
    }
  #pragma unroll
  for (int o=16;o>0;o>>=1) pn2 += __shfl_xor_sync(0xffffffffu, pn2, o);
  if (lane==0) swp[warp] = pn2;
  __syncthreads();
  if (tid < KCL) atomicAdd(&g_colnorm[b*KCL + tid], sCol[tid]);
  if (tid == 0){
    float t = 0.f;
    #pragma unroll
    for (int i=0;i<8;i++) t += swp[i];
    atomicAdd(&g_norm2[b], t);
  }
}

// ---------------- K5b: tiny — fold the two-stage norms into scale tables ----
__global__ __launch_bounds__(64) void scale_kernel(){
  int b = blockIdx.x, k = threadIdx.x;
  float cn = g_colnorm[b*KCL + k];
  float inv1 = 1.f / fmaxf(sqrtf(cn), 1e-12f);
  float contrib = cn * inv1 * inv1;
  float t = contrib;
  #pragma unroll
  for (int o=16;o>0;o>>=1) t += __shfl_xor_sync(0xffffffffu, t, o);
  __shared__ float sw[2];
  if ((k&31)==0) sw[k>>5] = t;
  __syncthreads();
  float n1 = sqrtf(sw[0] + sw[1]);
  g_scale1[b*KCL + k] = inv1 / fmaxf(n1, 1e-12f);
  if (k == 0) g_scale2[b] = 1.f / fmaxf(sqrtf(g_norm2[b]), 1e-12f);
}

// ---------------- K6: hidden1 via bf16 tensor cores (split emulation) -------
__global__ __launch_bounds__(256, 2) void gemm_fc1_hmma(
    const float* __restrict__ W){
  __shared__ uint AhS[2][32][12];
  __shared__ uint AlS[2][32][12];
  __shared__ float scl[BATCH*KCL];
  int tid = threadIdx.x;
  int warp = tid >> 5, lane = tid & 31;
  int i0 = blockIdx.y * 2048;
  int o0 = blockIdx.x * 256;

  const float* A;
  int iA0, half1;
  if (i0 < HALF1){ A = g_fv1; iA0 = i0; half1 = 1;
    for (int l = tid; l < BATCH*KCL; l += 256) scl[l] = g_scale1[l];
  } else { A = g_fv2; iA0 = i0 - HALF1; half1 = 0; }

  int bA = tid >> 3;
  int qA = tid & 7;
  float sc2b = half1 ? 1.f : g_scale2[bA];
  __syncthreads();

  int ncol = o0 + warp*32 + (lane >> 2);
  int krow = 2*(lane & 3);

  float acc[2][4][4];
  #pragma unroll
  for (int mt=0;mt<2;mt++)
    #pragma unroll
    for (int nt=0;nt<4;nt++)
      #pragma unroll
      for (int c=0;c<4;c++) acc[mt][nt][c] = 0.f;

  {
    int iAt = iA0;
    float2 av = *reinterpret_cast<const float2*>(&A[bA*HALF1 + iAt + 2*qA]);
    float s0, s1;
    if (half1){ int kk = (iAt + 2*qA) & 63; s0 = scl[bA*KCL+kk]; s1 = scl[bA*KCL+kk+1]; }
    else { s0 = sc2b; s1 = sc2b; }
    float v0 = av.x*s0, v1 = av.y*s1;
    AhS[0][bA][qA] = prmt_hi(v0, v1);
    AlS[0][bA][qA] = cvt_bf2(v1 - trunc_bf(v1), v0 - trunc_bf(v0));
  }
  float wcur[16];
  {
    const float* wp = W + (size_t)(i0 + krow)*OUTF + ncol;
    #pragma unroll
    for (int nt=0;nt<4;nt++){
      wcur[nt*4+0] = wp[nt*8];
      wcur[nt*4+1] = wp[nt*8 + OUTF];
      wcur[nt*4+2] = wp[nt*8 + 8*OUTF];
      wcur[nt*4+3] = wp[nt*8 + 9*OUTF];
    }
  }
  __syncthreads();

  const int T = 2048/16;
  for (int t=0; t<T; t++){
    int cur = t & 1;
    bool more = (t+1) < T;
    float wnxt[16]; float2 av; float s0=1.f, s1=1.f;
    if (more){
      const float* wp = W + (size_t)(i0 + (t+1)*16 + krow)*OUTF + ncol;
      #pragma unroll
      for (int nt=0;nt<4;nt++){
        wnxt[nt*4+0] = wp[nt*8];
        wnxt[nt*4+1] = wp[nt*8 + OUTF];
        wnxt[nt*4+2] = wp[nt*8 + 8*OUTF];
        wnxt[nt*4+3] = wp[nt*8 + 9*OUTF];
      }
      int iAt = iA0 + (t+1)*16;
      av = *reinterpret_cast<const float2*>(&A[bA*HALF1 + iAt + 2*qA]);
      if (half1){ int kk = (iAt + 2*qA) & 63; s0 = scl[bA*KCL+kk]; s1 = scl[bA*KCL+kk+1]; }
      else { s0 = sc2b; s1 = sc2b; }
    }
    uint ah[8], al[8];
    #pragma unroll
    for (int mt=0;mt<2;mt++){
      int r = (lane>>2) + mt*16;
      int c = lane & 3;
      ah[mt*4+0] = AhS[cur][r  ][c];
      ah[mt*4+1] = AhS[cur][r+8][c];
      ah[mt*4+2] = AhS[cur][r  ][c+4];
      ah[mt*4+3] = AhS[cur][r+8][c+4];
      al[mt*4+0] = AlS[cur][r  ][c];
      al[mt*4+1] = AlS[cur][r+8][c];
      al[mt*4+2] = AlS[cur][r  ][c+4];
      al[mt*4+3] = AlS[cur][r+8][c+4];
    }
    uint whi[8], wlo[8];
    #pragma unroll
    for (int nt=0;nt<4;nt++){
      float w0 = wcur[nt*4+0], w1 = wcur[nt*4+1];
      float w2 = wcur[nt*4+2], w3 = wcur[nt*4+3];
      whi[nt*2+0] = prmt_hi(w0, w1);
      whi[nt*2+1] = prmt_hi(w2, w3);
      wlo[nt*2+0] = cvt_bf2(w1 - trunc_bf(w1), w0 - trunc_bf(w0));
      wlo[nt*2+1] = cvt_bf2(w3 - trunc_bf(w3), w2 - trunc_bf(w2));
    }
    #pragma unroll
    for (int mt=0;mt<2;mt++){
      #pragma unroll
      for (int nt=0;nt<4;nt++){
        mma_bf16(acc[mt][nt], &ah[mt*4], whi[nt*2], whi[nt*2+1]);
        mma_bf16(acc[mt][nt], &al[mt*4], whi[nt*2], whi[nt*2+1]);
        mma_bf16(acc[mt][nt], &ah[mt*4], wlo[nt*2], wlo[nt*2+1]);
      }
    }
    if (more){
      float v0 = av.x*s0, v1 = av.y*s1;
      AhS[cur^1][bA][qA] = prmt_hi(v0, v1);
      AlS[cur^1][bA][qA] = cvt_bf2(v1 - trunc_bf(v1), v0 - trunc_bf(v0));
      #pragma unroll
      for (int p=0;p<16;p++) wcur[p] = wnxt[p];
    }
    __syncthreads();
  }

  #pragma unroll
  for (int mt=0;mt<2;mt++)
    #pragma unroll
    for (int nt=0;nt<4;nt++)
      #pragma unroll
      for (int c=0;c<4;c++){
        int row = (lane>>2) + ((c>=2)?8:0) + mt*16;
        int col = o0 + warp*32 + nt*8 + 2*(lane&3) + (c&1);
        atomicAdd(&g_fvout[row*OUTF + col], acc[mt][nt][c]);
      }
}

// ---------------- K7a: gating GEMM (fp32 FFMA2, small) ----------------------
#define FC_KT 16
__global__ __launch_bounds__(256) void gemm_fc_kernel(
    const float* __restrict__ W, int ichunk){
  __shared__ float Ws[2][FC_KT][256];
  __shared__ float fs[2][FC_KT][32];
  int tid = threadIdx.x;
  int o0 = blockIdx.x * 256;
  int i0 = blockIdx.y * ichunk;
  int og = tid & 63, bg = tid >> 6;
  const float* A = g_fvout; float* out = g_gates;
  int bload = tid & 31;
  int rload0 = (tid >> 5)*2;

  int T = ichunk / FC_KT;
  int roff[4], coff[4];
  #pragma unroll
  for (int p=0;p<4;p++){
    int off = p*1024 + tid*4;
    roff[p] = off >> 8; coff[p] = off & 255;
  }

  ull acc[8][2];
  #pragma unroll
  for (int bb=0;bb<8;bb++){ acc[bb][0]=0ull; acc[bb][1]=0ull; }

  float4 pw[4]; float pa0, pa1;
  {
    #pragma unroll
    for (int p=0;p<4;p++)
      pw[p] = *reinterpret_cast<const float4*>(&W[(i0+roff[p])*OUTF + o0 + coff[p]]);
    pa0 = A[bload*OUTF + i0 + rload0];
    pa1 = A[bload*OUTF + i0 + rload0 + 1];
  }
  #pragma unroll
  for (int p=0;p<4;p++)
    *reinterpret_cast<float4*>(&Ws[0][roff[p]][coff[p]]) = pw[p];
  fs[0][rload0][bload] = pa0;
  fs[0][rload0+1][bload] = pa1;
  __syncthreads();

  for (int t=0; t<T; t++){
    int cur = t & 1;
    bool more = (t+1) < T;
    if (more){
      int i  = i0 + (t+1)*FC_KT;
      #pragma unroll
      for (int p=0;p<4;p++)
        pw[p] = *reinterpret_cast<const float4*>(&W[(i+roff[p])*OUTF + o0 + coff[p]]);
      pa0 = A[bload*OUTF + i + rload0];
      pa1 = A[bload*OUTF + i + rload0 + 1];
    }
    #pragma unroll
    for (int ii=0; ii<FC_KT; ii++){
      const ull* wp = reinterpret_cast<const ull*>(&Ws[cur][ii][og*4]);
      ull w0 = wp[0], w1 = wp[1];
      float4 fa = *reinterpret_cast<const float4*>(&fs[cur][ii][bg*8]);
      float4 fb = *reinterpret_cast<const float4*>(&fs[cur][ii][bg*8+4]);
      ull a0 = pack2(fa.x,fa.x), a1 = pack2(fa.y,fa.y);
      ull a2 = pack2(fa.z,fa.z), a3 = pack2(fa.w,fa.w);
      ull a4 = pack2(fb.x,fb.x), a5 = pack2(fb.y,fb.y);
      ull a6 = pack2(fb.z,fb.z), a7 = pack2(fb.w,fb.w);
      ffma2(acc[0][0], a0, w0); ffma2(acc[0][1], a0, w1);
      ffma2(acc[1][0], a1, w0); ffma2(acc[1][1], a1, w1);
      ffma2(acc[2][0], a2, w0); ffma2(acc[2][1], a2, w1);
      ffma2(acc[3][0], a3, w0); ffma2(acc[3][1], a3, w1);
      ffma2(acc[4][0], a4, w0); ffma2(acc[4][1], a4, w1);
      ffma2(acc[5][0], a5, w0); ffma2(acc[5][1], a5, w1);
      ffma2(acc[6][0], a6, w0); ffma2(acc[6][1], a6, w1);
      ffma2(acc[7][0], a7, w0); ffma2(acc[7][1], a7, w1);
    }
    if (more){
      int nxt = (t+1) & 1;
      #pragma unroll
      for (int p=0;p<4;p++)
        *reinterpret_cast<float4*>(&Ws[nxt][roff[p]][coff[p]]) = pw[p];
      fs[nxt][rload0][bload] = pa0;
      fs[nxt][rload0+1][bload] = pa1;
    }
    __syncthreads();
  }

  #pragma unroll
  for (int bb=0;bb<8;bb++){
    int b = bg*8 + bb;
    #pragma unroll
    for (int t=0;t<2;t++){
      int base = b*OUTF + o0 + og*4 + t*2;
      atomicAdd(&out[base],   lo32(acc[bb][t]));
      atomicAdd(&out[base+1], hi32(acc[bb][t]));
    }
  }
}

// ---------------- K7b: BN2 (batch stats over 32) + sigmoid gate -------------
__global__ __launch_bounds__(256) void bn2_gate_kernel(
    const float* __restrict__ g2, const float* __restrict__ b2,
    float* __restrict__ out){
  int o = blockIdx.x*blockDim.x + threadIdx.x;   // 0..1023
  float m=0.f, s=0.f;
  #pragma unroll 8
  for (int b=0;b<BATCH;b++){ float v = g_gates[b*OUTF + o]; m += v; s += v*v; }
  m *= (1.f/BATCH);
  float var = s*(1.f/BATCH) - m*m;
  float rs = rsqrtf(var + 1e-5f);
  float ga = g2[o], be = b2[o];
  #pragma unroll 8
  for (int b=0;b<BATCH;b++){
    float v = (g_gates[b*OUTF + o] - m)*rs*ga + be;
    float sig = 1.f/(1.f + expf(-v));
    out[b*OUTF + o] = g_fvout[b*OUTF + o] * sig;
  }
}

// ---------------------------------------------------------------------------
extern "C" void kernel_launch(void* const* d_in, const int* in_sizes, int n_in,
                              void* d_out, int out_size){
  const float* x   = (const float*)d_in[0];   // [32,512,1024]
  const float* wc  = (const float*)d_in[1];   // [1024,64]
  const float* cov = (const float*)d_in[2];   // [1024,64]
  const float* cw2 = (const float*)d_in[3];   // [1,1024,64]
  const float* w1  = (const float*)d_in[4];   // [131072,1024]
  const float* g1  = (const float*)d_in[5];   // [64]
  const float* b1  = (const float*)d_in[6];   // [64]
  const float* wg  = (const float*)d_in[7];   // [1024,1024]
  const float* g2  = (const float*)d_in[8];   // [1024]
  const float* b2  = (const float*)d_in[9];   // [1024]
  float* out = (float*)d_out;                 // [32,1024]

  zero_kernel<<<128, 256>>>();
  gemm_act_kernel<<<256, 256>>>(x, wc);
  bn_softmax_kernel<<<2048, 256>>>(g1, b1);
  einsum_tc_kernel<<<dim3(16, 32), 256>>>(x, cov, cw2);
  scale_kernel<<<BATCH, 64>>>();
  gemm_fc1_hmma<<<dim3(4, 64), 256>>>(w1);           // hidden1 (tensor cores)
  gemm_fc_kernel<<<dim3(4, 8), 256>>>(wg, 128);      // gating (fp32)
  bn2_gate_kernel<<<4, 256>>>(g2, b2, out);
}

// round 12
// speedup vs baseline: 1.8201x; 1.0028x over previous
#include <cuda_runtime.h>

#define BATCH 32
#define NPTS 512
#define DIM 1024
#define KCL 64
#define NROWS (BATCH*NPTS)      /* 16384 */
#define OUTF 1024
#define IN2 (2*DIM*KCL)         /* 131072 */
#define HALF1 (DIM*KCL)         /* 65536 */

// ---------------- scratch (device globals: no allocations allowed) ----------
__device__ float g_act[NROWS*KCL];          // 4 MB
__device__ float g_colsum[KCL];
__device__ float g_colsumsq[KCL];
__device__ float g_asum[BATCH*KCL];
__device__ float g_fv1[BATCH*DIM*KCL];      // 8 MB
__device__ float g_fv2[BATCH*DIM*KCL];      // 8 MB
__device__ float g_colnorm[BATCH*KCL];
__device__ float g_norm2[BATCH];
__device__ float g_scale1[BATCH*KCL];
__device__ float g_scale2[BATCH];
__device__ float g_fvout[BATCH*OUTF];
__device__ float g_gates[BATCH*OUTF];

typedef unsigned long long ull;
typedef unsigned int uint;

// ---------------- f32x2 helpers (FFMA2: 2 FMAs / instr on sm_103a) ----------
__device__ __forceinline__ ull pack2(float lo, float hi){
  ull r;
  asm("mov.b64 %0, {%1, %2};" : "=l"(r)
      : "r"(__float_as_uint(lo)), "r"(__float_as_uint(hi)));
  return r;
}
__device__ __forceinline__ void ffma2(ull &d, ull a, ull b){
  asm("fma.rn.f32x2 %0, %1, %2, %3;" : "=l"(d) : "l"(a), "l"(b), "l"(d));
}
__device__ __forceinline__ float lo32(ull v){ return __uint_as_float((unsigned)(v & 0xffffffffull)); }
__device__ __forceinline__ float hi32(ull v){ return __uint_as_float((unsigned)(v >> 32)); }

// ---------------- bf16 split helpers ----------------------------------------
__device__ __forceinline__ uint prmt_hi(float a, float b){
  uint r;
  asm("prmt.b32 %0, %1, %2, 0x7632;" : "=r"(r)
      : "r"(__float_as_uint(a)), "r"(__float_as_uint(b)));
  return r;
}
__device__ __forceinline__ float trunc_bf(float v){
  return __uint_as_float(__float_as_uint(v) & 0xffff0000u);
}
__device__ __forceinline__ uint cvt_bf2(float upper, float lower){
  uint r;
  asm("cvt.rn.bf16x2.f32 %0, %1, %2;" : "=r"(r) : "f"(upper), "f"(lower));
  return r;
}
__device__ __forceinline__ void mma_bf16(float* c, const uint* a, uint b0, uint b1){
  asm volatile(
    "mma.sync.aligned.m16n8k16.row.col.f32.bf16.bf16.f32 "
    "{%0,%1,%2,%3},{%4,%5,%6,%7},{%8,%9},{%0,%1,%2,%3};"
    : "+f"(c[0]), "+f"(c[1]), "+f"(c[2]), "+f"(c[3])
    : "r"(a[0]), "r"(a[1]), "r"(a[2]), "r"(a[3]), "r"(b0), "r"(b1));
}

// ---------------- K0: zero the atomic accumulators ---------------------------
__global__ void zero_kernel(){
  int i = blockIdx.x*blockDim.x + threadIdx.x;
  if (i < BATCH*OUTF){ g_fvout[i] = 0.f; g_gates[i] = 0.f; }
  if (i < BATCH*KCL){ g_colnorm[i] = 0.f; g_asum[i] = 0.f; }
  if (i < KCL){ g_colsum[i] = 0.f; g_colsumsq[i] = 0.f; }
  if (i < BATCH) g_norm2[i] = 0.f;
}

// ---------------- K1: act_raw = X @ Wc  (+ column sum / sumsq for BN1) ------
__global__ __launch_bounds__(256) void gemm_act_kernel(
    const float* __restrict__ x, const float* __restrict__ wc){
  __shared__ float As[64][33];
  __shared__ float Bs[32][64];
  __shared__ float sSum[KCL], sSq[KCL];
  int tid = threadIdx.x;
  int row0 = blockIdx.x * 64;
  int tx = tid & 15, ty = tid >> 4;
  ull acc[4][2];
  #pragma unroll
  for (int i=0;i<4;i++){ acc[i][0]=0ull; acc[i][1]=0ull; }
  if (tid < KCL){ sSum[tid]=0.f; sSq[tid]=0.f; }

  for (int d0=0; d0<DIM; d0+=32){
    #pragma unroll
    for (int l=tid; l<2048; l+=256){
      int r=l>>5, c=l&31;
      As[r][c] = x[(row0+r)*DIM + d0 + c];
    }
    #pragma unroll
    for (int l=tid; l<2048; l+=256){
      int r=l>>6, c=l&63;
      Bs[r][c] = wc[(d0+r)*KCL + c];
    }
    __syncthreads();
    #pragma unroll
    for (int dd=0; dd<32; dd++){
      const ull* bp = reinterpret_cast<const ull*>(&Bs[dd][tx*4]);
      ull b0 = bp[0], b1 = bp[1];
      #pragma unroll
      for (int i=0;i<4;i++){
        float a = As[ty*4+i][dd];
        ull ap = pack2(a, a);
        ffma2(acc[i][0], ap, b0);
        ffma2(acc[i][1], ap, b1);
      }
    }
    __syncthreads();
  }
  float ps[4]={0,0,0,0}, pq[4]={0,0,0,0};
  #pragma unroll
  for (int i=0;i<4;i++){
    float v0=lo32(acc[i][0]), v1=hi32(acc[i][0]);
    float v2=lo32(acc[i][1]), v3=hi32(acc[i][1]);
    *reinterpret_cast<float4*>(&g_act[(row0+ty*4+i)*KCL + tx*4]) =
        make_float4(v0,v1,v2,v3);
    ps[0]+=v0; ps[1]+=v1; ps[2]+=v2; ps[3]+=v3;
    pq[0]+=v0*v0; pq[1]+=v1*v1; pq[2]+=v2*v2; pq[3]+=v3*v3;
  }
  #pragma unroll
  for (int j=0;j<4;j++){
    atomicAdd(&sSum[tx*4+j], ps[j]);
    atomicAdd(&sSq [tx*4+j], pq[j]);
  }
  __syncthreads();
  if (tid < KCL){
    atomicAdd(&g_colsum[tid],   sSum[tid]);
    atomicAdd(&g_colsumsq[tid], sSq[tid]);
  }
}

// ---------------- K2: BN1 + softmax (warp per row) + fused a_sum ------------
__global__ __launch_bounds__(256) void bn_softmax_kernel(
    const float* __restrict__ gamma, const float* __restrict__ beta){
  __shared__ float sbuf[8][KCL];
  int tid = threadIdx.x;
  int w = tid >> 5, lane = tid & 31;
  int row = blockIdx.x*8 + w;
  int b = row >> 9;
  const float inv_n = 1.f / (float)NROWS;
  int k2 = 2*lane;
  float2 cs = *reinterpret_cast<const float2*>(&g_colsum[k2]);
  float2 cq = *reinterpret_cast<const float2*>(&g_colsumsq[k2]);
  float2 ga = *reinterpret_cast<const float2*>(&gamma[k2]);
  float2 be = *reinterpret_cast<const float2*>(&beta[k2]);
  float m0 = cs.x*inv_n, m1 = cs.y*inv_n;
  float sc0 = ga.x*rsqrtf(cq.x*inv_n - m0*m0 + 1e-5f);
  float sc1 = ga.y*rsqrtf(cq.y*inv_n - m1*m1 + 1e-5f);
  float sh0 = be.x - m0*sc0, sh1 = be.y - m1*sc1;

  float2 v = *reinterpret_cast<const float2*>(&g_act[row*KCL + k2]);
  float vn0 = v.x*sc0 + sh0, vn1 = v.y*sc1 + sh1;
  float mx = fmaxf(vn0, vn1);
  #pragma unroll
  for (int o=16;o>0;o>>=1) mx = fmaxf(mx, __shfl_xor_sync(0xffffffffu, mx, o));
  float e0 = __expf(vn0 - mx), e1 = __expf(vn1 - mx);
  float s = e0 + e1;
  #pragma unroll
  for (int o=16;o>0;o>>=1) s += __shfl_xor_sync(0xffffffffu, s, o);
  float inv = 1.f / s;
  float p0 = e0*inv, p1 = e1*inv;
  *reinterpret_cast<float2*>(&g_act[row*KCL + k2]) = make_float2(p0, p1);
  *reinterpret_cast<float2*>(&sbuf[w][k2]) = make_float2(p0, p1);
  __syncthreads();
  if (tid < KCL){
    float t = 0.f;
    #pragma unroll
    for (int i=0;i<8;i++) t += sbuf[i][tid];
    atomicAdd(&g_asum[b*KCL + tid], t);
  }
}

// ---------------- K4: einsum via bf16 tensor cores + fused transform --------
__global__ __launch_bounds__(256, 2) void einsum_tc_kernel(
    const float* __restrict__ x,
    const float* __restrict__ covw, const float* __restrict__ cw2w){
  __shared__ uint aTh[2][64][12];
  __shared__ uint aTl[2][64][12];
  __shared__ uint xh[2][8][72];
  __shared__ uint xl[2][8][72];
  __shared__ uint qh[2][8][72];
  __shared__ uint ql[2][8][72];
  __shared__ float sAsum[KCL];
  __shared__ float sCol[KCL];
  __shared__ float swp[8];
  int tid = threadIdx.x, warp = tid >> 5, lane = tid & 31;
  int b = blockIdx.y, d0 = blockIdx.x * 64;
  int wm = warp & 1, wn = warp >> 1;
  int px  = tid >> 5;
  int dcx = (tid & 31) * 2;
  int ka  = tid & 63;
  int pa  = (tid >> 6) * 2;
  if (tid < KCL){ sAsum[tid] = g_asum[b*KCL + tid]; sCol[tid] = 0.f; }

  float acc1[2][2][4], acc2[2][2][4];
  #pragma unroll
  for (int mt=0;mt<2;mt++)
    #pragma unroll
    for (int nt=0;nt<2;nt++)
      #pragma unroll
      for (int c=0;c<4;c++){ acc1[mt][nt][c]=0.f; acc2[mt][nt][c]=0.f; }

  const float* xrow = x + (size_t)b*NPTS*DIM + d0;
  const float* arow = g_act + (size_t)b*NPTS*KCL;

  float xv[4], av[4];
  {
    float2 t0 = *reinterpret_cast<const float2*>(&xrow[(2*px  )*DIM + dcx]);
    float2 t1 = *reinterpret_cast<const float2*>(&xrow[(2*px+1)*DIM + dcx]);
    xv[0]=t0.x; xv[1]=t0.y; xv[2]=t1.x; xv[3]=t1.y;
    #pragma unroll
    for (int j=0;j<4;j++) av[j] = arow[(2*pa+j)*KCL + ka];
  }
  {
    float q0=xv[0]*xv[0], q1=xv[1]*xv[1], q2=xv[2]*xv[2], q3=xv[3]*xv[3];
    xh[0][px][dcx  ] = prmt_hi(xv[0], xv[2]);
    xh[0][px][dcx+1] = prmt_hi(xv[1], xv[3]);
    xl[0][px][dcx  ] = cvt_bf2(xv[2]-trunc_bf(xv[2]), xv[0]-trunc_bf(xv[0]));
    xl[0][px][dcx+1] = cvt_bf2(xv[3]-trunc_bf(xv[3]), xv[1]-trunc_bf(xv[1]));
    qh[0][px][dcx  ] = prmt_hi(q0, q2);
    qh[0][px][dcx+1] = prmt_hi(q1, q3);
    ql[0][px][dcx  ] = cvt_bf2(q2-trunc_bf(q2), q0-trunc_bf(q0));
    ql[0][px][dcx+1] = cvt_bf2(q3-trunc_bf(q3), q1-trunc_bf(q1));
    aTh[0][ka][pa  ] = prmt_hi(av[0], av[1]);
    aTh[0][ka][pa+1] = prmt_hi(av[2], av[3]);
    aTl[0][ka][pa  ] = cvt_bf2(av[1]-trunc_bf(av[1]), av[0]-trunc_bf(av[0]));
    aTl[0][ka][pa+1] = cvt_bf2(av[3]-trunc_bf(av[3]), av[2]-trunc_bf(av[2]));
  }
  __syncthreads();

  int r = lane >> 2, cfr = lane & 3;
  for (int t=0; t<32; t++){
    int cur = t & 1;
    bool more = (t+1) < 32;
    if (more){
      int n0 = (t+1)*16;
      float2 t0 = *reinterpret_cast<const float2*>(&xrow[(n0+2*px  )*DIM + dcx]);
      float2 t1 = *reinterpret_cast<const float2*>(&xrow[(n0+2*px+1)*DIM + dcx]);
      xv[0]=t0.x; xv[1]=t0.y; xv[2]=t1.x; xv[3]=t1.y;
      #pragma unroll
      for (int j=0;j<4;j++) av[j] = arow[(n0+2*pa+j)*KCL + ka];
    }
    uint ah[2][4], al[2][4];
    #pragma unroll
    for (int mt=0;mt<2;mt++){
      int rb = wm*32 + mt*16;
      ah[mt][0]=aTh[cur][rb+r  ][cfr];   ah[mt][1]=aTh[cur][rb+r+8][cfr];
      ah[mt][2]=aTh[cur][rb+r  ][cfr+4]; ah[mt][3]=aTh[cur][rb+r+8][cfr+4];
      al[mt][0]=aTl[cur][rb+r  ][cfr];   al[mt][1]=aTl[cur][rb+r+8][cfr];
      al[mt][2]=aTl[cur][rb+r  ][cfr+4]; al[mt][3]=aTl[cur][rb+r+8][cfr+4];
    }
    #pragma unroll
    for (int nt=0;nt<2;nt++){
      int col = wn*16 + nt*8 + r;
      uint bxh0 = xh[cur][cfr][col], bxh1 = xh[cur][cfr+4][col];
      uint bxl0 = xl[cur][cfr][col], bxl1 = xl[cur][cfr+4][col];
      uint bqh0 = qh[cur][cfr][col], bqh1 = qh[cur][cfr+4][col];
      uint bql0 = ql[cur][cfr][col], bql1 = ql[cur][cfr+4][col];
      #pragma unroll
      for (int mt=0;mt<2;mt++){
        mma_bf16(acc1[mt][nt], ah[mt], bxh0, bxh1);
        mma_bf16(acc1[mt][nt], al[mt], bxh0, bxh1);
        mma_bf16(acc1[mt][nt], ah[mt], bxl0, bxl1);
        mma_bf16(acc2[mt][nt], ah[mt], bqh0, bqh1);
        mma_bf16(acc2[mt][nt], al[mt], bqh0, bqh1);
        mma_bf16(acc2[mt][nt], ah[mt], bql0, bql1);
      }
    }
    if (more){
      int nxt = cur ^ 1;
      float q0=xv[0]*xv[0], q1=xv[1]*xv[1], q2=xv[2]*xv[2], q3=xv[3]*xv[3];
      xh[nxt][px][dcx  ] = prmt_hi(xv[0], xv[2]);
      xh[nxt][px][dcx+1] = prmt_hi(xv[1], xv[3]);
      xl[nxt][px][dcx  ] = cvt_bf2(xv[2]-trunc_bf(xv[2]), xv[0]-trunc_bf(xv[0]));
      xl[nxt][px][dcx+1] = cvt_bf2(xv[3]-trunc_bf(xv[3]), xv[1]-trunc_bf(xv[1]));
      qh[nxt][px][dcx  ] = prmt_hi(q0, q2);
      qh[nxt][px][dcx+1] = prmt_hi(q1, q3);
      ql[nxt][px][dcx  ] = cvt_bf2(q2-trunc_bf(q2), q0-trunc_bf(q0));
      ql[nxt][px][dcx+1] = cvt_bf2(q3-trunc_bf(q3), q1-trunc_bf(q1));
      aTh[nxt][ka][pa  ] = prmt_hi(av[0], av[1]);
      aTh[nxt][ka][pa+1] = prmt_hi(av[2], av[3]);
      aTl[nxt][ka][pa  ] = cvt_bf2(av[1]-trunc_bf(av[1]), av[0]-trunc_bf(av[0]));
      aTl[nxt][ka][pa+1] = cvt_bf2(av[3]-trunc_bf(av[3]), av[2]-trunc_bf(av[2]));
    }
    __syncthreads();
  }

  float pn2 = 0.f;
  float pcol[2][2] = {{0.f,0.f},{0.f,0.f}};
  #pragma unroll
  for (int mt=0;mt<2;mt++){
    #pragma unroll
    for (int nt=0;nt<2;nt++){
      #pragma unroll
      for (int c=0;c<4;c++){
        int k   = wm*32 + mt*16 + r + ((c>=2)?8:0);
        int dl  = wn*16 + nt*8 + 2*cfr + (c&1);
        int dgl = d0 + dl;
        int widx = dgl*KCL + k;
        float cwm = cw2w[widx];
        float cvm = covw[widx];
        float asum = sAsum[k];
        float cwv = cvm*cvm + 1e-6f;
        float rc = __fdividef(1.f, cwv);
        float f1r = acc1[mt][nt][c], f2r = acc2[mt][nt][c];
        float f1t = (f1r - asum*cwm) * rc;
        float f2t = (asum*cwm*cwm + f2r - 2.f*f1r*cwm) * rc * rc - asum;
        g_fv1[(b*DIM + dgl)*KCL + k] = f1t;
        g_fv2[(b*DIM + dgl)*KCL + k] = f2t;
        pcol[mt][c>>1 & 1] += f1t*f1t;
        pn2 += f2t*f2t;
      }
    }
  }
  #pragma unroll
  for (int mt=0;mt<2;mt++)
    #pragma unroll
    for (int h=0;h<2;h++){
      int k = wm*32 + mt*16 + r + h*8;
      atomicAdd(&sCol[k], pcol[mt][h]);
    }
  #pragma unroll
  for (int o=16;o>0;o>>=1) pn2 += __shfl_xor_sync(0xffffffffu, pn2, o);
  if (lane==0) swp[warp] = pn2;
  __syncthreads();
  if (tid < KCL) atomicAdd(&g_colnorm[b*KCL + tid], sCol[tid]);
  if (tid == 0){
    float t = 0.f;
    #pragma unroll
    for (int i=0;i<8;i++) t += swp[i];
    atomicAdd(&g_norm2[b], t);
  }
}

// ---------------- K5b: tiny — fold the two-stage norms into scale tables ----
__global__ __launch_bounds__(64) void scale_kernel(){
  int b = blockIdx.x, k = threadIdx.x;
  float cn = g_colnorm[b*KCL + k];
  float inv1 = 1.f / fmaxf(sqrtf(cn), 1e-12f);
  float contrib = cn * inv1 * inv1;
  float t = contrib;
  #pragma unroll
  for (int o=16;o>0;o>>=1) t += __shfl_xor_sync(0xffffffffu, t, o);
  __shared__ float sw[2];
  if ((k&31)==0) sw[k>>5] = t;
  __syncthreads();
  float n1 = sqrtf(sw[0] + sw[1]);
  g_scale1[b*KCL + k] = inv1 / fmaxf(n1, 1e-12f);
  if (k == 0) g_scale2[b] = 1.f / fmaxf(sqrtf(g_norm2[b]), 1e-12f);
}

// ---------------- K6: hidden1 bf16-TC, super-step A staging -----------------
// grid (4 o-tiles, 64 k-chunks of 2048), 256 thr. 16 super-steps of k128;
// A staged as split bf16 pairs [32][64] double-buffered (1 sync / 8 k16 steps),
// loaded as 4x LDG.128 per thread. W path: GMEM->regs, 1-step prefetch.
__global__ __launch_bounds__(256, 2) void gemm_fc1_hmma(
    const float* __restrict__ W){
  __shared__ uint AhS[2][32][68];
  __shared__ uint AlS[2][32][68];
  __shared__ float scl[BATCH*KCL];
  int tid = threadIdx.x;
  int warp = tid >> 5, lane = tid & 31;
  int i0 = blockIdx.y * 2048;
  int o0 = blockIdx.x * 256;

  const float* A;
  int iA0, half1;
  if (i0 < HALF1){ A = g_fv1; iA0 = i0; half1 = 1;
    for (int l = tid; l < BATCH*KCL; l += 256) scl[l] = g_scale1[l];
  } else { A = g_fv2; iA0 = i0 - HALF1; half1 = 0; }
  __syncthreads();

  // A staging role: 4x float4 = 16 consecutive k (8 pairs)
  int rA = tid >> 3;          // batch row 0..31
  int pA = (tid & 7) * 8;     // first pair index (pairs pA..pA+7)
  float sreg[16];
  if (half1){
    #pragma unroll
    for (int j=0;j<16;j++) sreg[j] = scl[rA*KCL + ((pA*2 + j) & 63)];
  } else {
    float s = g_scale2[rA];
    #pragma unroll
    for (int j=0;j<16;j++) sreg[j] = s;
  }

  int ncol = o0 + warp*32 + (lane >> 2);
  int krow = 2*(lane & 3);
  int r = lane >> 2, cfr = lane & 3;

  float acc[2][4][4];
  #pragma unroll
  for (int mt=0;mt<2;mt++)
    #pragma unroll
    for (int nt=0;nt<4;nt++)
      #pragma unroll
      for (int c=0;c<4;c++) acc[mt][nt][c] = 0.f;

  // ---- stage super-step 0 into buf 0 ----
  {
    const float* ap = &A[rA*HALF1 + iA0 + pA*2];
    float v[16];
    #pragma unroll
    for (int p=0;p<4;p++){
      float4 t4 = *reinterpret_cast<const float4*>(ap + p*4);
      v[p*4+0]=t4.x; v[p*4+1]=t4.y; v[p*4+2]=t4.z; v[p*4+3]=t4.w;
    }
    #pragma unroll
    for (int j=0;j<8;j++){
      float v0 = v[2*j]*sreg[2*j], v1 = v[2*j+1]*sreg[2*j+1];
      AhS[0][rA][pA+j] = prmt_hi(v0, v1);
      AlS[0][rA][pA+j] = cvt_bf2(v1 - trunc_bf(v1), v0 - trunc_bf(v0));
    }
  }
  // ---- preload W step 0 ----
  float wcur[16];
  {
    const float* wp = W + (size_t)(i0 + krow)*OUTF + ncol;
    #pragma unroll
    for (int nt=0;nt<4;nt++){
      wcur[nt*4+0] = wp[nt*8];
      wcur[nt*4+1] = wp[nt*8 + OUTF];
      wcur[nt*4+2] = wp[nt*8 + 8*OUTF];
      wcur[nt*4+3] = wp[nt*8 + 9*OUTF];
    }
  }
  __syncthreads();

  for (int ss=0; ss<16; ss++){
    int buf = ss & 1;
    bool moress = (ss+1) < 16;
    // load next super-step's A into registers (latency hidden by 8 steps)
    float vnext[16];
    if (moress){
      const float* ap = &A[rA*HALF1 + iA0 + (ss+1)*128 + pA*2];
      #pragma unroll
      for (int p=0;p<4;p++){
        float4 t4 = *reinterpret_cast<const float4*>(ap + p*4);
        vnext[p*4+0]=t4.x; vnext[p*4+1]=t4.y; vnext[p*4+2]=t4.z; vnext[p*4+3]=t4.w;
      }
    }
    // 8 inner k16 steps, no syncs
    #pragma unroll
    for (int s=0; s<8; s++){
      int t = ss*8 + s;
      float wnxt[16];
      bool moret = (t+1) < 128;
      if (moret){
        const float* wp = W + (size_t)(i0 + (t+1)*16 + krow)*OUTF + ncol;
        #pragma unroll
        for (int nt=0;nt<4;nt++){
          wnxt[nt*4+0] = wp[nt*8];
          wnxt[nt*4+1] = wp[nt*8 + OUTF];
          wnxt[nt*4+2] = wp[nt*8 + 8*OUTF];
          wnxt[nt*4+3] = wp[nt*8 + 9*OUTF];
        }
      }
      // A fragments (cols s*8 + cfr, +4)
      uint ah[8], al[8];
      #pragma unroll
      for (int mt=0;mt<2;mt++){
        int rr = r + mt*16;
        ah[mt*4+0] = AhS[buf][rr  ][s*8+cfr];
        ah[mt*4+1] = AhS[buf][rr+8][s*8+cfr];
        ah[mt*4+2] = AhS[buf][rr  ][s*8+cfr+4];
        ah[mt*4+3] = AhS[buf][rr+8][s*8+cfr+4];
        al[mt*4+0] = AlS[buf][rr  ][s*8+cfr];
        al[mt*4+1] = AlS[buf][rr+8][s*8+cfr];
        al[mt*4+2] = AlS[buf][rr  ][s*8+cfr+4];
        al[mt*4+3] = AlS[buf][rr+8][s*8+cfr+4];
      }
      // split current W
      uint whi[8], wlo[8];
      #pragma unroll
      for (int nt=0;nt<4;nt++){
        float w0 = wcur[nt*4+0], w1 = wcur[nt*4+1];
        float w2 = wcur[nt*4+2], w3 = wcur[nt*4+3];
        whi[nt*2+0] = prmt_hi(w0, w1);
        whi[nt*2+1] = prmt_hi(w2, w3);
        wlo[nt*2+0] = cvt_bf2(w1 - trunc_bf(w1), w0 - trunc_bf(w0));
        wlo[nt*2+1] = cvt_bf2(w3 - trunc_bf(w3), w2 - trunc_bf(w2));
      }
      #pragma unroll
      for (int mt=0;mt<2;mt++){
        #pragma unroll
        for (int nt=0;nt<4;nt++){
          mma_bf16(acc[mt][nt], &ah[mt*4], whi[nt*2], whi[nt*2+1]);
          mma_bf16(acc[mt][nt], &al[mt*4], whi[nt*2], whi[nt*2+1]);
          mma_bf16(acc[mt][nt], &ah[mt*4], wlo[nt*2], wlo[nt*2+1]);
        }
      }
      if (moret){
        #pragma unroll
        for (int p=0;p<16;p++) wcur[p] = wnxt[p];
      }
    }
    // stage next super-step into other buffer
    if (moress){
      int nb = buf ^ 1;
      #pragma unroll
      for (int j=0;j<8;j++){
        float v0 = vnext[2*j]*sreg[2*j], v1 = vnext[2*j+1]*sreg[2*j+1];
        AhS[nb][rA][pA+j] = prmt_hi(v0, v1);
        AlS[nb][rA][pA+j] = cvt_bf2(v1 - trunc_bf(v1), v0 - trunc_bf(v0));
      }
    }
    __syncthreads();
  }

  #pragma unroll
  for (int mt=0;mt<2;mt++)
    #pragma unroll
    for (int nt=0;nt<4;nt++)
      #pragma unroll
      for (int c=0;c<4;c++){
        int row = (lane>>2) + ((c>=2)?8:0) + mt*16;
        int col = o0 + warp*32 + nt*8 + 2*(lane&3) + (c&1);
        atomicAdd(&g_fvout[row*OUTF + col], acc[mt][nt][c]);
      }
}

// ---------------- K7a: gating GEMM (fp32 FFMA2, small) ----------------------
#define FC_KT 16
__global__ __launch_bounds__(256) void gemm_fc_kernel(
    const float* __restrict__ W, int ichunk){
  __shared__ float Ws[2][FC_KT][256];
  __shared__ float fs[2][FC_KT][32];
  int tid = threadIdx.x;
  int o0 = blockIdx.x * 256;
  int i0 = blockIdx.y * ichunk;
  int og = tid & 63, bg = tid >> 6;
  const float* A = g_fvout; float* out = g_gates;
  int bload = tid & 31;
  int rload0 = (tid >> 5)*2;

  int T = ichunk / FC_KT;
  int roff[4], coff[4];
  #pragma unroll
  for (int p=0;p<4;p++){
    int off = p*1024 + tid*4;
    roff[p] = off >> 8; coff[p] = off & 255;
  }

  ull acc[8][2];
  #pragma unroll
  for (int bb=0;bb<8;bb++){ acc[bb][0]=0ull; acc[bb][1]=0ull; }

  float4 pw[4]; float pa0, pa1;
  {
    #pragma unroll
    for (int p=0;p<4;p++)
      pw[p] = *reinterpret_cast<const float4*>(&W[(i0+roff[p])*OUTF + o0 + coff[p]]);
    pa0 = A[bload*OUTF + i0 + rload0];
    pa1 = A[bload*OUTF + i0 + rload0 + 1];
  }
  #pragma unroll
  for (int p=0;p<4;p++)
    *reinterpret_cast<float4*>(&Ws[0][roff[p]][coff[p]]) = pw[p];
  fs[0][rload0][bload] = pa0;
  fs[0][rload0+1][bload] = pa1;
  __syncthreads();

  for (int t=0; t<T; t++){
    int cur = t & 1;
    bool more = (t+1) < T;
    if (more){
      int i  = i0 + (t+1)*FC_KT;
      #pragma unroll
      for (int p=0;p<4;p++)
        pw[p] = *reinterpret_cast<const float4*>(&W[(i+roff[p])*OUTF + o0 + coff[p]]);
      pa0 = A[bload*OUTF + i + rload0];
      pa1 = A[bload*OUTF + i + rload0 + 1];
    }
    #pragma unroll
    for (int ii=0; ii<FC_KT; ii++){
      const ull* wp = reinterpret_cast<const ull*>(&Ws[cur][ii][og*4]);
      ull w0 = wp[0], w1 = wp[1];
      float4 fa = *reinterpret_cast<const float4*>(&fs[cur][ii][bg*8]);
      float4 fb = *reinterpret_cast<const float4*>(&fs[cur][ii][bg*8+4]);
      ull a0 = pack2(fa.x,fa.x), a1 = pack2(fa.y,fa.y);
      ull a2 = pack2(fa.z,fa.z), a3 = pack2(fa.w,fa.w);
      ull a4 = pack2(fb.x,fb.x), a5 = pack2(fb.y,fb.y);
      ull a6 = pack2(fb.z,fb.z), a7 = pack2(fb.w,fb.w);
      ffma2(acc[0][0], a0, w0); ffma2(acc[0][1], a0, w1);
      ffma2(acc[1][0], a1, w0); ffma2(acc[1][1], a1, w1);
      ffma2(acc[2][0], a2, w0); ffma2(acc[2][1], a2, w1);
      ffma2(acc[3][0], a3, w0); ffma2(acc[3][1], a3, w1);
      ffma2(acc[4][0], a4, w0); ffma2(acc[4][1], a4, w1);
      ffma2(acc[5][0], a5, w0); ffma2(acc[5][1], a5, w1);
      ffma2(acc[6][0], a6, w0); ffma2(acc[6][1], a6, w1);
      ffma2(acc[7][0], a7, w0); ffma2(acc[7][1], a7, w1);
    }
    if (more){
      int nxt = (t+1) & 1;
      #pragma unroll
      for (int p=0;p<4;p++)
        *reinterpret_cast<float4*>(&Ws[nxt][roff[p]][coff[p]]) = pw[p];
      fs[nxt][rload0][bload] = pa0;
      fs[nxt][rload0+1][bload] = pa1;
    }
    __syncthreads();
  }

  #pragma unroll
  for (int bb=0;bb<8;bb++){
    int b = bg*8 + bb;
    #pragma unroll
    for (int t=0;t<2;t++){
      int base = b*OUTF + o0 + og*4 + t*2;
      atomicAdd(&out[base],   lo32(acc[bb][t]));
      atomicAdd(&out[base+1], hi32(acc[bb][t]));
    }
  }
}

// ---------------- K7b: BN2 (batch stats over 32) + sigmoid gate -------------
__global__ __launch_bounds__(256) void bn2_gate_kernel(
    const float* __restrict__ g2, const float* __restrict__ b2,
    float* __restrict__ out){
  int o = blockIdx.x*blockDim.x + threadIdx.x;   // 0..1023
  float m=0.f, s=0.f;
  #pragma unroll 8
  for (int b=0;b<BATCH;b++){ float v = g_gates[b*OUTF + o]; m += v; s += v*v; }
  m *= (1.f/BATCH);
  float var = s*(1.f/BATCH) - m*m;
  float rs = rsqrtf(var + 1e-5f);
  float ga = g2[o], be = b2[o];
  #pragma unroll 8
  for (int b=0;b<BATCH;b++){
    float v = (g_gates[b*OUTF + o] - m)*rs*ga + be;
    float sig = 1.f/(1.f + expf(-v));
    out[b*OUTF + o] = g_fvout[b*OUTF + o] * sig;
  }
}

// ---------------------------------------------------------------------------
extern "C" void kernel_launch(void* const* d_in, const int* in_sizes, int n_in,
                              void* d_out, int out_size){
  const float* x   = (const float*)d_in[0];   // [32,512,1024]
  const float* wc  = (const float*)d_in[1];   // [1024,64]
  const float* cov = (const float*)d_in[2];   // [1024,64]
  const float* cw2 = (const float*)d_in[3];   // [1,1024,64]
  const float* w1  = (const float*)d_in[4];   // [131072,1024]
  const float* g1  = (const float*)d_in[5];   // [64]
  const float* b1  = (const float*)d_in[6];   // [64]
  const float* wg  = (const float*)d_in[7];   // [1024,1024]
  const float* g2  = (const float*)d_in[8];   // [1024]
  const float* b2  = (const float*)d_in[9];   // [1024]
  float* out = (float*)d_out;                 // [32,1024]

  zero_kernel<<<128, 256>>>();
  gemm_act_kernel<<<256, 256>>>(x, wc);
  bn_softmax_kernel<<<2048, 256>>>(g1, b1);
  einsum_tc_kernel<<<dim3(16, 32), 256>>>(x, cov, cw2);
  scale_kernel<<<BATCH, 64>>>();
  gemm_fc1_hmma<<<dim3(4, 64), 256>>>(w1);           // hidden1 (tensor cores)
  gemm_fc_kernel<<<dim3(4, 16), 256>>>(wg, 64);      // gating (fp32)
  bn2_gate_kernel<<<4, 256>>>(g2, b2, out);
}

// round 13
// speedup vs baseline: 2.0489x; 1.1257x over previous
#include <cuda_runtime.h>

#define BATCH 32
#define NPTS 512
#define DIM 1024
#define KCL 64
#define NROWS (BATCH*NPTS)      /* 16384 */
#define OUTF 1024
#define IN2 (2*DIM*KCL)         /* 131072 */
#define HALF1 (DIM*KCL)         /* 65536 */

// ---------------- scratch (device globals: no allocations allowed) ----------
__device__ float g_act[NROWS*KCL];          // 4 MB
__device__ float g_colsum[KCL];
__device__ float g_colsumsq[KCL];
__device__ float g_asum[BATCH*KCL];
__device__ float g_fv1[BATCH*DIM*KCL];      // 8 MB
__device__ float g_fv2[BATCH*DIM*KCL];      // 8 MB
__device__ float g_colnorm[BATCH*KCL];
__device__ float g_norm2[BATCH];
__device__ float g_scale1[BATCH*KCL];
__device__ float g_scale2[BATCH];
__device__ float g_fvout[BATCH*OUTF];
__device__ float g_gates[BATCH*OUTF];

typedef unsigned long long ull;
typedef unsigned int uint;

// ---------------- f32x2 helpers (FFMA2: 2 FMAs / instr on sm_103a) ----------
__device__ __forceinline__ ull pack2(float lo, float hi){
  ull r;
  asm("mov.b64 %0, {%1, %2};" : "=l"(r)
      : "r"(__float_as_uint(lo)), "r"(__float_as_uint(hi)));
  return r;
}
__device__ __forceinline__ void ffma2(ull &d, ull a, ull b){
  asm("fma.rn.f32x2 %0, %1, %2, %3;" : "=l"(d) : "l"(a), "l"(b), "l"(d));
}
__device__ __forceinline__ float lo32(ull v){ return __uint_as_float((unsigned)(v & 0xffffffffull)); }
__device__ __forceinline__ float hi32(ull v){ return __uint_as_float((unsigned)(v >> 32)); }

// ---------------- bf16 split helpers ----------------------------------------
__device__ __forceinline__ uint prmt_hi(float a, float b){
  uint r;
  asm("prmt.b32 %0, %1, %2, 0x7632;" : "=r"(r)
      : "r"(__float_as_uint(a)), "r"(__float_as_uint(b)));
  return r;
}
__device__ __forceinline__ float trunc_bf(float v){
  return __uint_as_float(__float_as_uint(v) & 0xffff0000u);
}
__device__ __forceinline__ uint cvt_bf2(float upper, float lower){
  uint r;
  asm("cvt.rn.bf16x2.f32 %0, %1, %2;" : "=r"(r) : "f"(upper), "f"(lower));
  return r;
}
__device__ __forceinline__ void mma_bf16(float* c, const uint* a, uint b0, uint b1){
  asm volatile(
    "mma.sync.aligned.m16n8k16.row.col.f32.bf16.bf16.f32 "
    "{%0,%1,%2,%3},{%4,%5,%6,%7},{%8,%9},{%0,%1,%2,%3};"
    : "+f"(c[0]), "+f"(c[1]), "+f"(c[2]), "+f"(c[3])
    : "r"(a[0]), "r"(a[1]), "r"(a[2]), "r"(a[3]), "r"(b0), "r"(b1));
}

// ---------------- K0: zero the atomic accumulators ---------------------------
__global__ void zero_kernel(){
  int i = blockIdx.x*blockDim.x + threadIdx.x;
  if (i < BATCH*OUTF){ g_fvout[i] = 0.f; g_gates[i] = 0.f; }
  if (i < BATCH*KCL){ g_colnorm[i] = 0.f; g_asum[i] = 0.f; }
  if (i < KCL){ g_colsum[i] = 0.f; g_colsumsq[i] = 0.f; }
  if (i < BATCH) g_norm2[i] = 0.f;
}

// ---------------- K1: act_raw = X @ Wc  (+ column sum / sumsq for BN1) ------
__global__ __launch_bounds__(256) void gemm_act_kernel(
    const float* __restrict__ x, const float* __restrict__ wc){
  __shared__ float As[64][33];
  __shared__ float Bs[32][64];
  __shared__ float sSum[KCL], sSq[KCL];
  int tid = threadIdx.x;
  int row0 = blockIdx.x * 64;
  int tx = tid & 15, ty = tid >> 4;
  ull acc[4][2];
  #pragma unroll
  for (int i=0;i<4;i++){ acc[i][0]=0ull; acc[i][1]=0ull; }
  if (tid < KCL){ sSum[tid]=0.f; sSq[tid]=0.f; }

  for (int d0=0; d0<DIM; d0+=32){
    #pragma unroll
    for (int l=tid; l<2048; l+=256){
      int r=l>>5, c=l&31;
      As[r][c] = x[(row0+r)*DIM + d0 + c];
    }
    #pragma unroll
    for (int l=tid; l<2048; l+=256){
      int r=l>>6, c=l&63;
      Bs[r][c] = wc[(d0+r)*KCL + c];
    }
    __syncthreads();
    #pragma unroll
    for (int dd=0; dd<32; dd++){
      const ull* bp = reinterpret_cast<const ull*>(&Bs[dd][tx*4]);
      ull b0 = bp[0], b1 = bp[1];
      #pragma unroll
      for (int i=0;i<4;i++){
        float a = As[ty*4+i][dd];
        ull ap = pack2(a, a);
        ffma2(acc[i][0], ap, b0);
        ffma2(acc[i][1], ap, b1);
      }
    }
    __syncthreads();
  }
  float ps[4]={0,0,0,0}, pq[4]={0,0,0,0};
  #pragma unroll
  for (int i=0;i<4;i++){
    float v0=lo32(acc[i][0]), v1=hi32(acc[i][0]);
    float v2=lo32(acc[i][1]), v3=hi32(acc[i][1]);
    *reinterpret_cast<float4*>(&g_act[(row0+ty*4+i)*KCL + tx*4]) =
        make_float4(v0,v1,v2,v3);
    ps[0]+=v0; ps[1]+=v1; ps[2]+=v2; ps[3]+=v3;
    pq[0]+=v0*v0; pq[1]+=v1*v1; pq[2]+=v2*v2; pq[3]+=v3*v3;
  }
  #pragma unroll
  for (int j=0;j<4;j++){
    atomicAdd(&sSum[tx*4+j], ps[j]);
    atomicAdd(&sSq [tx*4+j], pq[j]);
  }
  __syncthreads();
  if (tid < KCL){
    atomicAdd(&g_colsum[tid],   sSum[tid]);
    atomicAdd(&g_colsumsq[tid], sSq[tid]);
  }
}

// ---------------- K2: BN1 + softmax (warp per row) + fused a_sum ------------
__global__ __launch_bounds__(256) void bn_softmax_kernel(
    const float* __restrict__ gamma, const float* __restrict__ beta){
  __shared__ float sbuf[8][KCL];
  int tid = threadIdx.x;
  int w = tid >> 5, lane = tid & 31;
  int row = blockIdx.x*8 + w;
  int b = row >> 9;
  const float inv_n = 1.f / (float)NROWS;
  int k2 = 2*lane;
  float2 cs = *reinterpret_cast<const float2*>(&g_colsum[k2]);
  float2 cq = *reinterpret_cast<const float2*>(&g_colsumsq[k2]);
  float2 ga = *reinterpret_cast<const float2*>(&gamma[k2]);
  float2 be = *reinterpret_cast<const float2*>(&beta[k2]);
  float m0 = cs.x*inv_n, m1 = cs.y*inv_n;
  float sc0 = ga.x*rsqrtf(cq.x*inv_n - m0*m0 + 1e-5f);
  float sc1 = ga.y*rsqrtf(cq.y*inv_n - m1*m1 + 1e-5f);
  float sh0 = be.x - m0*sc0, sh1 = be.y - m1*sc1;

  float2 v = *reinterpret_cast<const float2*>(&g_act[row*KCL + k2]);
  float vn0 = v.x*sc0 + sh0, vn1 = v.y*sc1 + sh1;
  float mx = fmaxf(vn0, vn1);
  #pragma unroll
  for (int o=16;o>0;o>>=1) mx = fmaxf(mx, __shfl_xor_sync(0xffffffffu, mx, o));
  float e0 = __expf(vn0 - mx), e1 = __expf(vn1 - mx);
  float s = e0 + e1;
  #pragma unroll
  for (int o=16;o>0;o>>=1) s += __shfl_xor_sync(0xffffffffu, s, o);
  float inv = 1.f / s;
  float p0 = e0*inv, p1 = e1*inv;
  *reinterpret_cast<float2*>(&g_act[row*KCL + k2]) = make_float2(p0, p1);
  *reinterpret_cast<float2*>(&sbuf[w][k2]) = make_float2(p0, p1);
  __syncthreads();
  if (tid < KCL){
    float t = 0.f;
    #pragma unroll
    for (int i=0;i<8;i++) t += sbuf[i][tid];
    atomicAdd(&g_asum[b*KCL + tid], t);
  }
}

// ---------------- K4: einsum via bf16 tensor cores + fused transform --------
__global__ __launch_bounds__(256, 2) void einsum_tc_kernel(
    const float* __restrict__ x,
    const float* __restrict__ covw, const float* __restrict__ cw2w){
  __shared__ uint aTh[2][64][12];
  __shared__ uint aTl[2][64][12];
  __shared__ uint xh[2][8][72];
  __shared__ uint xl[2][8][72];
  __shared__ uint qh[2][8][72];
  __shared__ uint ql[2][8][72];
  __shared__ float sAsum[KCL];
  __shared__ float sCol[KCL];
  __shared__ float swp[8];
  int tid = threadIdx.x, warp = tid >> 5, lane = tid & 31;
  int b = blockIdx.y, d0 = blockIdx.x * 64;
  int wm = warp & 1, wn = warp >> 1;
  int px  = tid >> 5;
  int dcx = (tid & 31) * 2;
  int ka  = tid & 63;
  int pa  = (tid >> 6) * 2;
  if (tid < KCL){ sAsum[tid] = g_asum[b*KCL + tid]; sCol[tid] = 0.f; }

  float acc1[2][2][4], acc2[2][2][4];
  #pragma unroll
  for (int mt=0;mt<2;mt++)
    #pragma unroll
    for (int nt=0;nt<2;nt++)
      #pragma unroll
      for (int c=0;c<4;c++){ acc1[mt][nt][c]=0.f; acc2[mt][nt][c]=0.f; }

  const float* xrow = x + (size_t)b*NPTS*DIM + d0;
  const float* arow = g_act + (size_t)b*NPTS*KCL;

  float xv[4], av[4];
  {
    float2 t0 = *reinterpret_cast<const float2*>(&xrow[(2*px  )*DIM + dcx]);
    float2 t1 = *reinterpret_cast<const float2*>(&xrow[(2*px+1)*DIM + dcx]);
    xv[0]=t0.x; xv[1]=t0.y; xv[2]=t1.x; xv[3]=t1.y;
    #pragma unroll
    for (int j=0;j<4;j++) av[j] = arow[(2*pa+j)*KCL + ka];
  }
  {
    float q0=xv[0]*xv[0], q1=xv[1]*xv[1], q2=xv[2]*xv[2], q3=xv[3]*xv[3];
    xh[0][px][dcx  ] = prmt_hi(xv[0], xv[2]);
    xh[0][px][dcx+1] = prmt_hi(xv[1], xv[3]);
    xl[0][px][dcx  ] = cvt_bf2(xv[2]-trunc_bf(xv[2]), xv[0]-trunc_bf(xv[0]));
    xl[0][px][dcx+1] = cvt_bf2(xv[3]-trunc_bf(xv[3]), xv[1]-trunc_bf(xv[1]));
    qh[0][px][dcx  ] = prmt_hi(q0, q2);
    qh[0][px][dcx+1] = prmt_hi(q1, q3);
    ql[0][px][dcx  ] = cvt_bf2(q2-trunc_bf(q2), q0-trunc_bf(q0));
    ql[0][px][dcx+1] = cvt_bf2(q3-trunc_bf(q3), q1-trunc_bf(q1));
    aTh[0][ka][pa  ] = prmt_hi(av[0], av[1]);
    aTh[0][ka][pa+1] = prmt_hi(av[2], av[3]);
    aTl[0][ka][pa  ] = cvt_bf2(av[1]-trunc_bf(av[1]), av[0]-trunc_bf(av[0]));
    aTl[0][ka][pa+1] = cvt_bf2(av[3]-trunc_bf(av[3]), av[2]-trunc_bf(av[2]));
  }
  __syncthreads();

  int r = lane >> 2, cfr = lane & 3;
  for (int t=0; t<32; t++){
    int cur = t & 1;
    bool more = (t+1) < 32;
    if (more){
      int n0 = (t+1)*16;
      float2 t0 = *reinterpret_cast<const float2*>(&xrow[(n0+2*px  )*DIM + dcx]);
      float2 t1 = *reinterpret_cast<const float2*>(&xrow[(n0+2*px+1)*DIM + dcx]);
      xv[0]=t0.x; xv[1]=t0.y; xv[2]=t1.x; xv[3]=t1.y;
      #pragma unroll
      for (int j=0;j<4;j++) av[j] = arow[(n0+2*pa+j)*KCL + ka];
    }
    uint ah[2][4], al[2][4];
    #pragma unroll
    for (int mt=0;mt<2;mt++){
      int rb = wm*32 + mt*16;
      ah[mt][0]=aTh[cur][rb+r  ][cfr];   ah[mt][1]=aTh[cur][rb+r+8][cfr];
      ah[mt][2]=aTh[cur][rb+r  ][cfr+4]; ah[mt][3]=aTh[cur][rb+r+8][cfr+4];
      al[mt][0]=aTl[cur][rb+r  ][cfr];   al[mt][1]=aTl[cur][rb+r+8][cfr];
      al[mt][2]=aTl[cur][rb+r  ][cfr+4]; al[mt][3]=aTl[cur][rb+r+8][cfr+4];
    }
    #pragma unroll
    for (int nt=0;nt<2;nt++){
      int col = wn*16 + nt*8 + r;
      uint bxh0 = xh[cur][cfr][col], bxh1 = xh[cur][cfr+4][col];
      uint bxl0 = xl[cur][cfr][col], bxl1 = xl[cur][cfr+4][col];
      uint bqh0 = qh[cur][cfr][col], bqh1 = qh[cur][cfr+4][col];
      uint bql0 = ql[cur][cfr][col], bql1 = ql[cur][cfr+4][col];
      #pragma unroll
      for (int mt=0;mt<2;mt++){
        mma_bf16(acc1[mt][nt], ah[mt], bxh0, bxh1);
        mma_bf16(acc1[mt][nt], al[mt], bxh0, bxh1);
        mma_bf16(acc1[mt][nt], ah[mt], bxl0, bxl1);
        mma_bf16(acc2[mt][nt], ah[mt], bqh0, bqh1);
        mma_bf16(acc2[mt][nt], al[mt], bqh0, bqh1);
        mma_bf16(acc2[mt][nt], ah[mt], bql0, bql1);
      }
    }
    if (more){
      int nxt = cur ^ 1;
      float q0=xv[0]*xv[0], q1=xv[1]*xv[1], q2=xv[2]*xv[2], q3=xv[3]*xv[3];
      xh[nxt][px][dcx  ] = prmt_hi(xv[0], xv[2]);
      xh[nxt][px][dcx+1] = prmt_hi(xv[1], xv[3]);
      xl[nxt][px][dcx  ] = cvt_bf2(xv[2]-trunc_bf(xv[2]), xv[0]-trunc_bf(xv[0]));
      xl[nxt][px][dcx+1] = cvt_bf2(xv[3]-trunc_bf(xv[3]), xv[1]-trunc_bf(xv[1]));
      qh[nxt][px][dcx  ] = prmt_hi(q0, q2);
      qh[nxt][px][dcx+1] = prmt_hi(q1, q3);
      ql[nxt][px][dcx  ] = cvt_bf2(q2-trunc_bf(q2), q0-trunc_bf(q0));
      ql[nxt][px][dcx+1] = cvt_bf2(q3-trunc_bf(q3), q1-trunc_bf(q1));
      aTh[nxt][ka][pa  ] = prmt_hi(av[0], av[1]);
      aTh[nxt][ka][pa+1] = prmt_hi(av[2], av[3]);
      aTl[nxt][ka][pa  ] = cvt_bf2(av[1]-trunc_bf(av[1]), av[0]-trunc_bf(av[0]));
      aTl[nxt][ka][pa+1] = cvt_bf2(av[3]-trunc_bf(av[3]), av[2]-trunc_bf(av[2]));
    }
    __syncthreads();
  }

  float pn2 = 0.f;
  float pcol[2][2] = {{0.f,0.f},{0.f,0.f}};
  #pragma unroll
  for (int mt=0;mt<2;mt++){
    #pragma unroll
    for (int nt=0;nt<2;nt++){
      #pragma unroll
      for (int c=0;c<4;c++){
        int k   = wm*32 + mt*16 + r + ((c>=2)?8:0);
        int dl  = wn*16 + nt*8 + 2*cfr + (c&1);
        int dgl = d0 + dl;
        int widx = dgl*KCL + k;
        float cwm = cw2w[widx];
        float cvm = covw[widx];
        float asum = sAsum[k];
        float cwv = cvm*cvm + 1e-6f;
        float rc = __fdividef(1.f, cwv);
        float f1r = acc1[mt][nt][c], f2r = acc2[mt][nt][c];
        float f1t = (f1r - asum*cwm) * rc;
        float f2t = (asum*cwm*cwm + f2r - 2.f*f1r*cwm) * rc * rc - asum;
        g_fv1[(b*DIM + dgl)*KCL + k] = f1t;
        g_fv2[(b*DIM + dgl)*KCL + k] = f2t;
        pcol[mt][c>>1 & 1] += f1t*f1t;
        pn2 += f2t*f2t;
      }
    }
  }
  #pragma unroll
  for (int mt=0;mt<2;mt++)
    #pragma unroll
    for (int h=0;h<2;h++){
      int k = wm*32 + mt*16 + r + h*8;
      atomicAdd(&sCol[k], pcol[mt][h]);
    }
  #pragma unroll
  for (int o=16;o>0;o>>=1) pn2 += __shfl_xor_sync(0xffffffffu, pn2, o);
  if (lane==0) swp[warp] = pn2;
  __syncthreads();
  if (tid < KCL) atomicAdd(&g_colnorm[b*KCL + tid], sCol[tid]);
  if (tid == 0){
    float t = 0.f;
    #pragma unroll
    for (int i=0;i<8;i++) t += swp[i];
    atomicAdd(&g_norm2[b], t);
  }
}

// ---------------- K5b: tiny — fold the two-stage norms into scale tables ----
__global__ __launch_bounds__(64) void scale_kernel(){
  int b = blockIdx.x, k = threadIdx.x;
  float cn = g_colnorm[b*KCL + k];
  float inv1 = 1.f / fmaxf(sqrtf(cn), 1e-12f);
  float contrib = cn * inv1 * inv1;
  float t = contrib;
  #pragma unroll
  for (int o=16;o>0;o>>=1) t += __shfl_xor_sync(0xffffffffu, t, o);
  __shared__ float sw[2];
  if ((k&31)==0) sw[k>>5] = t;
  __syncthreads();
  float n1 = sqrtf(sw[0] + sw[1]);
  g_scale1[b*KCL + k] = inv1 / fmaxf(n1, 1e-12f);
  if (k == 0) g_scale2[b] = 1.f / fmaxf(sqrtf(g_norm2[b]), 1e-12f);
}

// ---------------- K6: hidden1 bf16-TC with cp.async 4-stage W pipeline ------
// grid (4 o-tiles, 64 k-chunks of 2048), 256 thr, dynamic smem:
//   Ws ring: 4 stages x [16][260] fp32 (66560 B), conflict-free LDS (stride 260)
//   A: split bf16 pairs [2][32][68] x2 (34816 B)          total 101376 B
// W loads GMEM->smem via cp.async.cg (load->use window = 3 steps ~1200cyc).
#define FC1_WPAD 260
#define FC1_SMEM (4*16*FC1_WPAD*4 + 2*32*68*4*2)
__global__ __launch_bounds__(256, 2) void gemm_fc1_hmma(
    const float* __restrict__ W){
  extern __shared__ char smemraw[];
  float (*WsS)[16][FC1_WPAD] = reinterpret_cast<float(*)[16][FC1_WPAD]>(smemraw);
  uint (*AhS)[32][68] = reinterpret_cast<uint(*)[32][68]>(smemraw + 4*16*FC1_WPAD*4);
  uint (*AlS)[32][68] = reinterpret_cast<uint(*)[32][68]>(smemraw + 4*16*FC1_WPAD*4 + 2*32*68*4);

  int tid = threadIdx.x;
  int warp = tid >> 5, lane = tid & 31;
  int i0 = blockIdx.y * 2048;
  int o0 = blockIdx.x * 256;

  const float* A;
  int iA0, half1;
  if (i0 < HALF1){ A = g_fv1; iA0 = i0; half1 = 1; }
  else { A = g_fv2; iA0 = i0 - HALF1; half1 = 0; }

  // A staging role: 4x float4 = 16 consecutive k (8 pairs)
  int rA = tid >> 3;          // batch row 0..31
  int pA = (tid & 7) * 8;     // first pair index
  float sreg[16];
  if (half1){
    #pragma unroll
    for (int j=0;j<16;j++) sreg[j] = g_scale1[rA*KCL + ((pA*2 + j) & 63)];
  } else {
    float s = g_scale2[rA];
    #pragma unroll
    for (int j=0;j<16;j++) sreg[j] = s;
  }

  // W cp.async role: 4 x 16B chunks per stage
  int wrow0 = tid >> 6;            // +p*4
  int wcol0 = (tid & 63) * 4;

  int wcol = warp*32 + (lane >> 2);    // local o-col for fragments
  int krow = 2*(lane & 3);
  int r = lane >> 2, cfr = lane & 3;

  float acc[2][4][4];
  #pragma unroll
  for (int mt=0;mt<2;mt++)
    #pragma unroll
    for (int nt=0;nt<4;nt++)
      #pragma unroll
      for (int c=0;c<4;c++) acc[mt][nt][c] = 0.f;

  // ---- prologue: issue W stages 0..2 ----
  #pragma unroll
  for (int s=0; s<3; s++){
    const float* base = W + (size_t)(i0 + s*16)*OUTF + o0;
    #pragma unroll
    for (int p=0;p<4;p++){
      int row = wrow0 + p*4;
      uint dst = (uint)__cvta_generic_to_shared(&WsS[s][row][wcol0]);
      const float* src = base + row*OUTF + wcol0;
      asm volatile("cp.async.cg.shared.global [%0], [%1], 16;" :: "r"(dst), "l"(src));
    }
    asm volatile("cp.async.commit_group;");
  }

  // ---- stage A super-step 0 into buf 0 ----
  {
    const float* ap = &A[rA*HALF1 + iA0 + pA*2];
    float v[16];
    #pragma unroll
    for (int p=0;p<4;p++){
      float4 t4 = *reinterpret_cast<const float4*>(ap + p*4);
      v[p*4+0]=t4.x; v[p*4+1]=t4.y; v[p*4+2]=t4.z; v[p*4+3]=t4.w;
    }
    #pragma unroll
    for (int j=0;j<8;j++){
      float v0 = v[2*j]*sreg[2*j], v1 = v[2*j+1]*sreg[2*j+1];
      AhS[0][rA][pA+j] = prmt_hi(v0, v1);
      AlS[0][rA][pA+j] = cvt_bf2(v1 - trunc_bf(v1), v0 - trunc_bf(v0));
    }
  }
  asm volatile("cp.async.wait_group 2;");
  __syncthreads();

  float vnext[16];
  for (int t=0; t<128; t++){
    int st = t & 3;
    int ss = t >> 3, sin = t & 7, buf = ss & 1;
    // issue W stage for step t+3
    if (t+3 < 128){
      const float* base = W + (size_t)(i0 + (t+3)*16)*OUTF + o0;
      int s = (t+3) & 3;
      #pragma unroll
      for (int p=0;p<4;p++){
        int row = wrow0 + p*4;
        uint dst = (uint)__cvta_generic_to_shared(&WsS[s][row][wcol0]);
        const float* src = base + row*OUTF + wcol0;
        asm volatile("cp.async.cg.shared.global [%0], [%1], 16;" :: "r"(dst), "l"(src));
      }
      asm volatile("cp.async.commit_group;");
    }
    // A next-super-step register load at start of super-step
    if (sin == 0 && ss+1 < 16){
      const float* ap = &A[rA*HALF1 + iA0 + (ss+1)*128 + pA*2];
      #pragma unroll
      for (int p=0;p<4;p++){
        float4 t4 = *reinterpret_cast<const float4*>(ap + p*4);
        vnext[p*4+0]=t4.x; vnext[p*4+1]=t4.y; vnext[p*4+2]=t4.z; vnext[p*4+3]=t4.w;
      }
    }
    // W fragments from smem stage st (conflict-free: bank = (4*row+col)%32)
    float wcur[16];
    #pragma unroll
    for (int nt=0;nt<4;nt++){
      wcur[nt*4+0] = WsS[st][krow  ][wcol + nt*8];
      wcur[nt*4+1] = WsS[st][krow+1][wcol + nt*8];
      wcur[nt*4+2] = WsS[st][krow+8][wcol + nt*8];
      wcur[nt*4+3] = WsS[st][krow+9][wcol + nt*8];
    }
    // A fragments
    uint ah[8], al[8];
    #pragma unroll
    for (int mt=0;mt<2;mt++){
      int rr = r + mt*16;
      ah[mt*4+0] = AhS[buf][rr  ][sin*8+cfr];
      ah[mt*4+1] = AhS[buf][rr+8][sin*8+cfr];
      ah[mt*4+2] = AhS[buf][rr  ][sin*8+cfr+4];
      ah[mt*4+3] = AhS[buf][rr+8][sin*8+cfr+4];
      al[mt*4+0] = AlS[buf][rr  ][sin*8+cfr];
      al[mt*4+1] = AlS[buf][rr+8][sin*8+cfr];
      al[mt*4+2] = AlS[buf][rr  ][sin*8+cfr+4];
      al[mt*4+3] = AlS[buf][rr+8][sin*8+cfr+4];
    }
    // split current W
    uint whi[8], wlo[8];
    #pragma unroll
    for (int nt=0;nt<4;nt++){
      float w0 = wcur[nt*4+0], w1 = wcur[nt*4+1];
      float w2 = wcur[nt*4+2], w3 = wcur[nt*4+3];
      whi[nt*2+0] = prmt_hi(w0, w1);
      whi[nt*2+1] = prmt_hi(w2, w3);
      wlo[nt*2+0] = cvt_bf2(w1 - trunc_bf(w1), w0 - trunc_bf(w0));
      wlo[nt*2+1] = cvt_bf2(w3 - trunc_bf(w3), w2 - trunc_bf(w2));
    }
    #pragma unroll
    for (int mt=0;mt<2;mt++){
      #pragma unroll
      for (int nt=0;nt<4;nt++){
        mma_bf16(acc[mt][nt], &ah[mt*4], whi[nt*2], whi[nt*2+1]);
        mma_bf16(acc[mt][nt], &al[mt*4], whi[nt*2], whi[nt*2+1]);
        mma_bf16(acc[mt][nt], &ah[mt*4], wlo[nt*2], wlo[nt*2+1]);
      }
    }
    // stage next A super-step at end of this one (visible after barrier below)
    if (sin == 7 && ss+1 < 16){
      int nb = buf ^ 1;
      #pragma unroll
      for (int j=0;j<8;j++){
        float v0 = vnext[2*j]*sreg[2*j], v1 = vnext[2*j+1]*sreg[2*j+1];
        AhS[nb][rA][pA+j] = prmt_hi(v0, v1);
        AlS[nb][rA][pA+j] = cvt_bf2(v1 - trunc_bf(v1), v0 - trunc_bf(v0));
      }
    }
    if (t+1 < 128){
      if (t+3 < 128){ asm volatile("cp.async.wait_group 2;"); }
      else          { asm volatile("cp.async.wait_group 0;"); }
      __syncthreads();
    }
  }

  #pragma unroll
  for (int mt=0;mt<2;mt++)
    #pragma unroll
    for (int nt=0;nt<4;nt++)
      #pragma unroll
      for (int c=0;c<4;c++){
        int row = (lane>>2) + ((c>=2)?8:0) + mt*16;
        int col = o0 + warp*32 + nt*8 + 2*(lane&3) + (c&1);
        atomicAdd(&g_fvout[row*OUTF + col], acc[mt][nt][c]);
      }
}

// ---------------- K7a: gating GEMM (fp32 FFMA2, small) ----------------------
#define FC_KT 16
__global__ __launch_bounds__(256) void gemm_fc_kernel(
    const float* __restrict__ W, int ichunk){
  __shared__ float Ws[2][FC_KT][256];
  __shared__ float fs[2][FC_KT][32];
  int tid = threadIdx.x;
  int o0 = blockIdx.x * 256;
  int i0 = blockIdx.y * ichunk;
  int og = tid & 63, bg = tid >> 6;
  const float* A = g_fvout; float* out = g_gates;
  int bload = tid & 31;
  int rload0 = (tid >> 5)*2;

  int T = ichunk / FC_KT;
  int roff[4], coff[4];
  #pragma unroll
  for (int p=0;p<4;p++){
    int off = p*1024 + tid*4;
    roff[p] = off >> 8; coff[p] = off & 255;
  }

  ull acc[8][2];
  #pragma unroll
  for (int bb=0;bb<8;bb++){ acc[bb][0]=0ull; acc[bb][1]=0ull; }

  float4 pw[4]; float pa0, pa1;
  {
    #pragma unroll
    for (int p=0;p<4;p++)
      pw[p] = *reinterpret_cast<const float4*>(&W[(i0+roff[p])*OUTF + o0 + coff[p]]);
    pa0 = A[bload*OUTF + i0 + rload0];
    pa1 = A[bload*OUTF + i0 + rload0 + 1];
  }
  #pragma unroll
  for (int p=0;p<4;p++)
    *reinterpret_cast<float4*>(&Ws[0][roff[p]][coff[p]]) = pw[p];
  fs[0][rload0][bload] = pa0;
  fs[0][rload0+1][bload] = pa1;
  __syncthreads();

  for (int t=0; t<T; t++){
    int cur = t & 1;
    bool more = (t+1) < T;
    if (more){
      int i  = i0 + (t+1)*FC_KT;
      #pragma unroll
      for (int p=0;p<4;p++)
        pw[p] = *reinterpret_cast<const float4*>(&W[(i+roff[p])*OUTF + o0 + coff[p]]);
      pa0 = A[bload*OUTF + i + rload0];
      pa1 = A[bload*OUTF + i + rload0 + 1];
    }
    #pragma unroll
    for (int ii=0; ii<FC_KT; ii++){
      const ull* wp = reinterpret_cast<const ull*>(&Ws[cur][ii][og*4]);
      ull w0 = wp[0], w1 = wp[1];
      float4 fa = *reinterpret_cast<const float4*>(&fs[cur][ii][bg*8]);
      float4 fb = *reinterpret_cast<const float4*>(&fs[cur][ii][bg*8+4]);
      ull a0 = pack2(fa.x,fa.x), a1 = pack2(fa.y,fa.y);
      ull a2 = pack2(fa.z,fa.z), a3 = pack2(fa.w,fa.w);
      ull a4 = pack2(fb.x,fb.x), a5 = pack2(fb.y,fb.y);
      ull a6 = pack2(fb.z,fb.z), a7 = pack2(fb.w,fb.w);
      ffma2(acc[0][0], a0, w0); ffma2(acc[0][1], a0, w1);
      ffma2(acc[1][0], a1, w0); ffma2(acc[1][1], a1, w1);
      ffma2(acc[2][0], a2, w0); ffma2(acc[2][1], a2, w1);
      ffma2(acc[3][0], a3, w0); ffma2(acc[3][1], a3, w1);
      ffma2(acc[4][0], a4, w0); ffma2(acc[4][1], a4, w1);
      ffma2(acc[5][0], a5, w0); ffma2(acc[5][1], a5, w1);
      ffma2(acc[6][0], a6, w0); ffma2(acc[6][1], a6, w1);
      ffma2(acc[7][0], a7, w0); ffma2(acc[7][1], a7, w1);
    }
    if (more){
      int nxt = (t+1) & 1;
      #pragma unroll
      for (int p=0;p<4;p++)
        *reinterpret_cast<float4*>(&Ws[nxt][roff[p]][coff[p]]) = pw[p];
      fs[nxt][rload0][bload] = pa0;
      fs[nxt][rload0+1][bload] = pa1;
    }
    __syncthreads();
  }

  #pragma unroll
  for (int bb=0;bb<8;bb++){
    int b = bg*8 + bb;
    #pragma unroll
    for (int t=0;t<2;t++){
      int base = b*OUTF + o0 + og*4 + t*2;
      atomicAdd(&out[base],   lo32(acc[bb][t]));
      atomicAdd(&out[base+1], hi32(acc[bb][t]));
    }
  }
}

// ---------------- K7b: BN2 (batch stats over 32) + sigmoid gate -------------
__global__ __launch_bounds__(256) void bn2_gate_kernel(
    const float* __restrict__ g2, const float* __restrict__ b2,
    float* __restrict__ out){
  int o = blockIdx.x*blockDim.x + threadIdx.x;   // 0..1023
  float m=0.f, s=0.f;
  #pragma unroll 8
  for (int b=0;b<BATCH;b++){ float v = g_gates[b*OUTF + o]; m += v; s += v*v; }
  m *= (1.f/BATCH);
  float var = s*(1.f/BATCH) - m*m;
  float rs = rsqrtf(var + 1e-5f);
  float ga = g2[o], be = b2[o];
  #pragma unroll 8
  for (int b=0;b<BATCH;b++){
    float v = (g_gates[b*OUTF + o] - m)*rs*ga + be;
    float sig = 1.f/(1.f + expf(-v));
    out[b*OUTF + o] = g_fvout[b*OUTF + o] * sig;
  }
}

// ---------------------------------------------------------------------------
extern "C" void kernel_launch(void* const* d_in, const int* in_sizes, int n_in,
                              void* d_out, int out_size){
  const float* x   = (const float*)d_in[0];   // [32,512,1024]
  const float* wc  = (const float*)d_in[1];   // [1024,64]
  const float* cov = (const float*)d_in[2];   // [1024,64]
  const float* cw2 = (const float*)d_in[3];   // [1,1024,64]
  const float* w1  = (const float*)d_in[4];   // [131072,1024]
  const float* g1  = (const float*)d_in[5];   // [64]
  const float* b1  = (const float*)d_in[6];   // [64]
  const float* wg  = (const float*)d_in[7];   // [1024,1024]
  const float* g2  = (const float*)d_in[8];   // [1024]
  const float* b2  = (const float*)d_in[9];   // [1024]
  float* out = (float*)d_out;                 // [32,1024]

  // attribute set (idempotent, host-side, not a stream op / allocation)
  cudaFuncSetAttribute(gemm_fc1_hmma,
      cudaFuncAttributeMaxDynamicSharedMemorySize, FC1_SMEM);

  zero_kernel<<<128, 256>>>();
  gemm_act_kernel<<<256, 256>>>(x, wc);
  bn_softmax_kernel<<<2048, 256>>>(g1, b1);
  einsum_tc_kernel<<<dim3(16, 32), 256>>>(x, cov, cw2);
  scale_kernel<<<BATCH, 64>>>();
  gemm_fc1_hmma<<<dim3(4, 64), 256, FC1_SMEM>>>(w1); // hidden1 (TC + cp.async)
  gemm_fc_kernel<<<dim3(4, 16), 256>>>(wg, 64);      // gating (fp32)
  bn2_gate_kernel<<<4, 256>>>(g2, b2, out);
}